// round 12
// baseline (speedup 1.0000x reference)
#include <cuda_runtime.h>
#include <cuda_fp16.h>
#include <math.h>

#define E 1024
#define H 16
#define D 64
#define B 4
#define S 1024
#define NROWS (B*S)     // 4096
#define FFDIM 2048
#define ATT_SCALE 0.03125f    // 1/sqrt(1024) = 2^-5 (exact in fp16)

// ------------------------- scratch (no allocations allowed) -----------------
__device__ __half g_qh[NROWS * E];
__device__ __half g_kh[NROWS * E];
__device__ __half g_vh[NROWS * E];
__device__ __half g_Wqh[E * E];
__device__ __half g_Wkh[E * E];
__device__ __half g_Wvh[E * E];
__device__ __half g_Woh[E * E];
__device__ __half g_W1h[E * FFDIM];
__device__ __half g_W2h[FFDIM * E];
__device__ __half g_qph[NROWS * E];
__device__ __half g_kph[NROWS * E];
__device__ __half g_vph[NROWS * E];
__device__ __half g_attnh[NROWS * E];
__device__ float  g_att[NROWS * E];
__device__ __half g_hh[NROWS * E];
__device__ __half g_g1h[NROWS * FFDIM];
__device__ float  g_ff[NROWS * E];
__device__ int    g_mq[NROWS];
__device__ int    g_mk[NROWS];

// ------------------------- mask canonicalization -----------------------------
__device__ __forceinline__ void mask_conv_one(const void* raw, int* out, int n,
                                              int tid, int nthr, int* s_flags) {
    const unsigned char* p = (const unsigned char*)raw;
    int big = 0, nonal = 0;
    for (int i = tid; i < n; i += nthr) {
        unsigned char v = p[i];
        if (v > 1) big = 1;
        if ((i & 3) != 0 && v != 0) nonal = 1;
    }
    if (big)   atomicOr(&s_flags[0], 1);
    if (nonal) atomicOr(&s_flags[1], 1);
    __syncthreads();
    int kind = s_flags[0] ? 2 : (s_flags[1] ? 1 : 0);
    for (int i = tid; i < n; i += nthr) {
        int v;
        if (kind == 2)      v = (((const float*)raw)[i] != 0.0f);
        else if (kind == 1) v = (p[i] != 0);
        else                v = (((const int*)raw)[i] != 0);
        out[i] = v;
    }
}
__global__ void mask_convert2_kernel(const void* __restrict__ rawk, int* __restrict__ outk,
                                     const void* __restrict__ rawq, int* __restrict__ outq,
                                     int n) {
    __shared__ int fk[2], fq[2];
    if (threadIdx.x == 0) { fk[0] = fk[1] = fq[0] = fq[1] = 0; }
    __syncthreads();
    mask_conv_one(rawk, outk, n, threadIdx.x, blockDim.x, fk);
    __syncthreads();
    mask_conv_one(rawq, outq, n, threadIdx.x, blockDim.x, fq);
}

// ------------------------- fused fp32 -> fp16 conversion ---------------------
// Segment picked by blockIdx.y (no per-element branching).
#define Q_NE (NROWS * E / 4)     // 1048576
#define Q_EE (E * E / 4)         // 262144
#define Q_EF (E * FFDIM / 4)     // 524288

__global__ __launch_bounds__(256)
void f2h_all_kernel(const float* s0, __half* d0, const float* s1, __half* d1,
                    const float* s2, __half* d2, const float* s3, __half* d3,
                    const float* s4, __half* d4, const float* s5, __half* d5,
                    const float* s6, __half* d6, const float* s7, __half* d7,
                    const float* s8, __half* d8) {
    const float* src; __half* dst; int n4;
    switch (blockIdx.y) {
        case 0: src = s0; dst = d0; n4 = Q_NE; break;
        case 1: src = s1; dst = d1; n4 = Q_NE; break;
        case 2: src = s2; dst = d2; n4 = Q_NE; break;
        case 3: src = s3; dst = d3; n4 = Q_EE; break;
        case 4: src = s4; dst = d4; n4 = Q_EE; break;
        case 5: src = s5; dst = d5; n4 = Q_EE; break;
        case 6: src = s6; dst = d6; n4 = Q_EE; break;
        case 7: src = s7; dst = d7; n4 = Q_EF; break;
        default: src = s8; dst = d8; n4 = Q_EF; break;
    }
    int i = blockIdx.x * blockDim.x + threadIdx.x;
    const int stride = gridDim.x * blockDim.x;
    for (; i < n4; i += stride) {
        float4 v = ((const float4*)src)[i];
        __half2* o = (__half2*)dst + 2 * i;
        o[0] = __floats2half2_rn(v.x, v.y);
        o[1] = __floats2half2_rn(v.z, v.w);
    }
}

// ------------------------- mma / ldmatrix helpers ----------------------------
__device__ __forceinline__ unsigned h2u(__half2 h) {
    union { __half2 h; unsigned u; } c; c.h = h; return c.u;
}
__device__ __forceinline__ unsigned u2hm(unsigned u, __half2 s) {
    union { __half2 h; unsigned u; } c; c.u = u;
    c.h = __hmul2(c.h, s);
    return c.u;
}
__device__ __forceinline__ void mma16(float c[4], const unsigned a[4], const unsigned b[2]) {
    asm volatile(
        "mma.sync.aligned.m16n8k16.row.col.f32.f16.f16.f32 "
        "{%0,%1,%2,%3}, {%4,%5,%6,%7}, {%8,%9}, {%0,%1,%2,%3};"
        : "+f"(c[0]), "+f"(c[1]), "+f"(c[2]), "+f"(c[3])
        : "r"(a[0]), "r"(a[1]), "r"(a[2]), "r"(a[3]), "r"(b[0]), "r"(b[1]));
}
__device__ __forceinline__ void ldsm4(unsigned r[4], unsigned saddr) {
    asm volatile("ldmatrix.sync.aligned.m8n8.x4.shared.b16 {%0,%1,%2,%3}, [%4];"
                 : "=r"(r[0]), "=r"(r[1]), "=r"(r[2]), "=r"(r[3]) : "r"(saddr));
}
__device__ __forceinline__ void ldsm4t(unsigned r[4], unsigned saddr) {
    asm volatile("ldmatrix.sync.aligned.m8n8.x4.trans.shared.b16 {%0,%1,%2,%3}, [%4];"
                 : "=r"(r[0]), "=r"(r[1]), "=r"(r[2]), "=r"(r[3]) : "r"(saddr));
}
__device__ __forceinline__ void cp16(void* smem, const void* g) {
    unsigned s = (unsigned)__cvta_generic_to_shared(smem);
    asm volatile("cp.async.cg.shared.global [%0], [%1], 16;\n" :: "r"(s), "l"(g));
}
__device__ __forceinline__ void cp_commit() { asm volatile("cp.async.commit_group;\n"); }
template<int N> __device__ __forceinline__ void cp_wait() {
    asm volatile("cp.async.wait_group %0;\n" :: "n"(N));
}

// ------------------------- fp16 tensor-core GEMM (round 11) ------------------
#define ASTR 40
#define BSTR 136
#define GSTAGES 4
#define STAGE_H (128 * ASTR + 32 * BSTR)           // 9472 halfs per stage
#define GEMM_SMEM_BYTES (GSTAGES * STAGE_H * 2)    // 75776 B

template<int EPI, typename OutT, bool QKV3>
__global__ __launch_bounds__(128, 2)
void tc_gemm(const __half* __restrict__ A0, const __half* __restrict__ B0,
             const __half* __restrict__ A1, const __half* __restrict__ B1,
             const __half* __restrict__ A2, const __half* __restrict__ B2,
             const float* __restrict__ bias, OutT* __restrict__ C0,
             OutT* __restrict__ C1, OutT* __restrict__ C2,
             int M, int N, int K) {
    extern __shared__ __half smem[];
    const __half* A = A0; const __half* Bm = B0; OutT* C = C0;
    if (QKV3) {
        if (blockIdx.z == 1) { A = A1; Bm = B1; C = C1; }
        else if (blockIdx.z == 2) { A = A2; Bm = B2; C = C2; }
    }
    const int tid = threadIdx.x;
    const int bm = blockIdx.y * 128, bn = blockIdx.x * 128;
    const int warp = tid >> 5, lane = tid & 31;
    const int wm = (warp & 1) * 64;
    const int wn = (warp >> 1) * 64;
    const int g = lane >> 2, t4 = lane & 3;
    const int l16 = lane & 15, lhi = (lane & 16) ? 8 : 0;

    const unsigned sbase = (unsigned)__cvta_generic_to_shared(smem);

    float c[4][8][4];
#pragma unroll
    for (int i = 0; i < 4; i++)
#pragma unroll
        for (int j = 0; j < 8; j++)
#pragma unroll
            for (int r = 0; r < 4; r++) c[i][j][r] = 0.0f;

    auto load_stage = [&](int buf, int tI) {
        __half* As = smem + buf * STAGE_H;
        __half* Bs = As + 128 * ASTR;
#pragma unroll
        for (int q = 0; q < 4; q++) {
            int ch = tid + 128 * q;
            int ar = ch >> 2, acc_ = (ch & 3) * 8;
            cp16(&As[ar * ASTR + acc_], A + (size_t)(bm + ar) * K + tI * 32 + acc_);
            int brr = ch >> 4, bcc = (ch & 15) * 8;
            cp16(&Bs[brr * BSTR + bcc], Bm + (size_t)(tI * 32 + brr) * N + bn + bcc);
        }
    };

    const int T = K / 32;
#pragma unroll
    for (int s = 0; s < GSTAGES - 1; s++) {
        load_stage(s, s);
        cp_commit();
    }

    for (int tI = 0; tI < T; tI++) {
        const int buf = tI & (GSTAGES - 1);
        cp_wait<GSTAGES - 2>();
        __syncthreads();
        if (tI + GSTAGES - 1 < T)
            load_stage((tI + GSTAGES - 1) & (GSTAGES - 1), tI + GSTAGES - 1);
        cp_commit();

        const unsigned sA = sbase + 2u * (buf * STAGE_H);
        const unsigned sB = sA + 2u * (128 * ASTR);
#pragma unroll
        for (int step = 0; step < 2; step++) {
            const int k0 = step * 16;
            unsigned af[4][4], bf[8][2];
#pragma unroll
            for (int i = 0; i < 4; i++) {
                unsigned addr = sA + 2u * ((wm + i * 16 + l16) * ASTR + k0 + lhi);
                ldsm4(af[i], addr);
            }
#pragma unroll
            for (int jp = 0; jp < 4; jp++) {
                unsigned addr = sB + 2u * ((k0 + l16) * BSTR + wn + jp * 16 + lhi);
                unsigned r[4];
                ldsm4t(r, addr);
                bf[2 * jp][0] = r[0];     bf[2 * jp][1] = r[1];
                bf[2 * jp + 1][0] = r[2]; bf[2 * jp + 1][1] = r[3];
            }
#pragma unroll
            for (int i = 0; i < 4; i++)
#pragma unroll
                for (int j = 0; j < 8; j++)
                    mma16(c[i][j], af[i], bf[j]);
        }
    }

#pragma unroll
    for (int i = 0; i < 4; i++) {
#pragma unroll
        for (int j = 0; j < 8; j++) {
            const int row0 = bm + wm + i * 16 + g;
            const int col = bn + wn + j * 8 + 2 * t4;
            float v0 = c[i][j][0], v1 = c[i][j][1], v2 = c[i][j][2], v3 = c[i][j][3];
            if (EPI >= 1) {
                float b0 = bias[col], b1 = bias[col + 1];
                v0 += b0; v1 += b1; v2 += b0; v3 += b1;
            }
            if (EPI == 2) {
                v0 *= 1.0f / (1.0f + __expf(-1.702f * v0));
                v1 *= 1.0f / (1.0f + __expf(-1.702f * v1));
                v2 *= 1.0f / (1.0f + __expf(-1.702f * v2));
                v3 *= 1.0f / (1.0f + __expf(-1.702f * v3));
            }
            if (sizeof(OutT) == 2) {
                *(__half2*)((__half*)C + (size_t)row0 * N + col) = __floats2half2_rn(v0, v1);
                *(__half2*)((__half*)C + (size_t)(row0 + 8) * N + col) = __floats2half2_rn(v2, v3);
            } else {
                float2 p0 = {v0, v1}, p1 = {v2, v3};
                *(float2*)((float*)C + (size_t)row0 * N + col) = p0;
                *(float2*)((float*)C + (size_t)(row0 + 8) * N + col) = p1;
            }
        }
    }
}

// ------------------------- fp16 tensor-core flash attention ------------------
// 128 q x (b,h); 4 warps x 32 q rows. KB=64 keys per buffer (two 32-key
// compute halves) -> half the barriers/waits of round 11. Q pre-scaled by
// 2^-5 in fp16 (exact) so scores need no fp32 scale before exp.
#define KVSTR 72
#define KB 64

__global__ __launch_bounds__(128)
void attn_tc_kernel(const __half* __restrict__ qp, const __half* __restrict__ kp,
                    const __half* __restrict__ vp, const int* __restrict__ mq,
                    const int* __restrict__ mk, __half* __restrict__ out) {
    __shared__ __half Ks[2][KB * KVSTR];
    __shared__ __half Vs[2][KB * KVSTR];
    __shared__ float kmS[2][KB];

    const int b = blockIdx.z, h = blockIdx.y;
    const int q0 = blockIdx.x * 128;
    const int tid = threadIdx.x;
    const int w = tid >> 5, lane = tid & 31;
    const int g = lane >> 2, t4 = lane & 3;
    const int l16 = lane & 15, lhi = (lane & 16) ? 8 : 0;
    const int l8 = lane & 7, lm = ((lane & 8) ? 8 : 0), ln16 = (lane & 16) ? 8 : 0;

    const unsigned sK0 = (unsigned)__cvta_generic_to_shared(&Ks[0][0]);
    const unsigned sK1 = (unsigned)__cvta_generic_to_shared(&Ks[1][0]);
    const unsigned sV0 = (unsigned)__cvta_generic_to_shared(&Vs[0][0]);
    const unsigned sV1 = (unsigned)__cvta_generic_to_shared(&Vs[1][0]);

    // Q fragments, pre-scaled by 2^-5 (exact power-of-two in fp16)
    const __half2 qscale = __float2half2_rn(ATT_SCALE);
    unsigned qa[2][4][4];
#pragma unroll
    for (int i = 0; i < 2; i++) {
        const __half* Qr0 = qp + (size_t)(b * S + q0 + w * 32 + i * 16 + g) * E + h * D;
        const __half* Qr1 = Qr0 + (size_t)8 * E;
#pragma unroll
        for (int s = 0; s < 4; s++) {
            qa[i][s][0] = u2hm(*(const unsigned*)&Qr0[16 * s + 2 * t4], qscale);
            qa[i][s][1] = u2hm(*(const unsigned*)&Qr1[16 * s + 2 * t4], qscale);
            qa[i][s][2] = u2hm(*(const unsigned*)&Qr0[16 * s + 8 + 2 * t4], qscale);
            qa[i][s][3] = u2hm(*(const unsigned*)&Qr1[16 * s + 8 + 2 * t4], qscale);
        }
    }

    float oacc[2][8][4];
#pragma unroll
    for (int i = 0; i < 2; i++)
#pragma unroll
        for (int n = 0; n < 8; n++)
#pragma unroll
            for (int r = 0; r < 4; r++) oacc[i][n][r] = 0.0f;
    float lsum[2][2] = {{0.0f, 0.0f}, {0.0f, 0.0f}};

    auto load_tiles = [&](int kt, int buf) {
        // 64 keys x 64 halfs per tensor: each thread 1 key x 32 halfs (4 cp16)
        int key = tid >> 1, c16 = (tid & 1) * 32;
        const __half* gk = kp + (size_t)(b * S + kt + key) * E + h * D + c16;
        const __half* gv = vp + (size_t)(b * S + kt + key) * E + h * D + c16;
        cp16(&Ks[buf][key * KVSTR + c16], gk);
        cp16(&Ks[buf][key * KVSTR + c16 + 8], gk + 8);
        cp16(&Ks[buf][key * KVSTR + c16 + 16], gk + 16);
        cp16(&Ks[buf][key * KVSTR + c16 + 24], gk + 24);
        cp16(&Vs[buf][key * KVSTR + c16], gv);
        cp16(&Vs[buf][key * KVSTR + c16 + 8], gv + 8);
        cp16(&Vs[buf][key * KVSTR + c16 + 16], gv + 16);
        cp16(&Vs[buf][key * KVSTR + c16 + 24], gv + 24);
        if (tid < KB) kmS[buf][tid] = mk[b * S + kt + tid] ? 1.0f : 0.0f;
    };

    load_tiles(0, 0);
    cp_commit();

    for (int kb = 0; kb < S / KB; kb++) {
        const int buf = kb & 1;
        if (kb + 1 < S / KB) {
            load_tiles((kb + 1) * KB, buf ^ 1);
            cp_commit();
            cp_wait<1>();
        } else {
            cp_wait<0>();
        }
        __syncthreads();

        const unsigned sK = buf ? sK1 : sK0;
        const unsigned sV = buf ? sV1 : sV0;

#pragma unroll
        for (int hf = 0; hf < 2; hf++) {
            const int ko = hf * 32;   // key offset within buffer

            // --- S = Q @ K^T over 32 keys ---
            float sc[2][4][4];
#pragma unroll
            for (int i = 0; i < 2; i++)
#pragma unroll
                for (int j = 0; j < 4; j++)
#pragma unroll
                    for (int r = 0; r < 4; r++) sc[i][j][r] = 0.0f;
#pragma unroll
            for (int s = 0; s < 4; s++) {
#pragma unroll
                for (int jp = 0; jp < 2; jp++) {
                    unsigned addr = sK + 2u * ((ko + jp * 16 + l8 + ln16) * KVSTR + 16 * s + lm);
                    unsigned r[4];
                    ldsm4(r, addr);
                    unsigned bf0[2] = {r[0], r[1]};
                    unsigned bf1[2] = {r[2], r[3]};
#pragma unroll
                    for (int i = 0; i < 2; i++) {
                        mma16(sc[i][2 * jp], qa[i][s], bf0);
                        mma16(sc[i][2 * jp + 1], qa[i][s], bf1);
                    }
                }
            }

            // --- P = exp(S)*mask (Q pre-scaled); pack; row sums ---
            unsigned pp[2][4][2];
#pragma unroll
            for (int i = 0; i < 2; i++) {
#pragma unroll
                for (int j = 0; j < 4; j++) {
                    const int c0 = ko + 8 * j + 2 * t4;
                    float m0 = kmS[buf][c0], m1 = kmS[buf][c0 + 1];
                    float p0 = __expf(sc[i][j][0]) * m0;
                    float p1 = __expf(sc[i][j][1]) * m1;
                    float p2 = __expf(sc[i][j][2]) * m0;
                    float p3 = __expf(sc[i][j][3]) * m1;
                    lsum[i][0] += p0 + p1;
                    lsum[i][1] += p2 + p3;
                    pp[i][j][0] = h2u(__floats2half2_rn(p0, p1));
                    pp[i][j][1] = h2u(__floats2half2_rn(p2, p3));
                }
            }

            // --- O += P @ V over 32 keys ---
#pragma unroll
            for (int s = 0; s < 2; s++) {
                unsigned pa[2][4];
#pragma unroll
                for (int i = 0; i < 2; i++) {
                    pa[i][0] = pp[i][2 * s][0]; pa[i][1] = pp[i][2 * s][1];
                    pa[i][2] = pp[i][2 * s + 1][0]; pa[i][3] = pp[i][2 * s + 1][1];
                }
#pragma unroll
                for (int np = 0; np < 4; np++) {
                    unsigned addr = sV + 2u * ((ko + 16 * s + l16) * KVSTR + np * 16 + lhi);
                    unsigned r[4];
                    ldsm4t(r, addr);
                    unsigned bf0[2] = {r[0], r[1]};
                    unsigned bf1[2] = {r[2], r[3]};
#pragma unroll
                    for (int i = 0; i < 2; i++) {
                        mma16(oacc[i][2 * np], pa[i], bf0);
                        mma16(oacc[i][2 * np + 1], pa[i], bf1);
                    }
                }
            }
        }
        __syncthreads();
    }

#pragma unroll
    for (int i = 0; i < 2; i++) {
        float l0 = lsum[i][0], l1 = lsum[i][1];
        l0 += __shfl_xor_sync(0xffffffffu, l0, 1);
        l0 += __shfl_xor_sync(0xffffffffu, l0, 2);
        l1 += __shfl_xor_sync(0xffffffffu, l1, 1);
        l1 += __shfl_xor_sync(0xffffffffu, l1, 2);

        const int row0 = b * S + q0 + w * 32 + i * 16 + g;
        const float inv0 = mq[row0] ? 1.0f / l0 : 0.0f;
        const float inv1 = mq[row0 + 8] ? 1.0f / l1 : 0.0f;
        __half* o0 = out + (size_t)row0 * E + h * D;
        __half* o1 = o0 + (size_t)8 * E;
#pragma unroll
        for (int n = 0; n < 8; n++) {
            const int c0 = 8 * n + 2 * t4;
            *(__half2*)(o0 + c0) = __floats2half2_rn(oacc[i][n][0] * inv0, oacc[i][n][1] * inv0);
            *(__half2*)(o1 + c0) = __floats2half2_rn(oacc[i][n][2] * inv1, oacc[i][n][3] * inv1);
        }
    }
}

// ------------------------- layernorm + mask + residual -----------------------
template<int MODE, typename OutT>
__global__ __launch_bounds__(256)
void ln_kernel(const float* __restrict__ x, const float* __restrict__ res,
               const float* __restrict__ g, const float* __restrict__ bb,
               const int* __restrict__ mask, OutT* __restrict__ out) {
    __shared__ float s1[256], s2[256];
    const int row = blockIdx.x;
    const int tid = threadIdx.x;
    const float* xr = x + (size_t)row * E;
    const float* rr = res + (size_t)row * E;
    float v[4];
    float s = 0.0f, sq = 0.0f;
#pragma unroll
    for (int i = 0; i < 4; i++) {
        int c = tid + i * 256;
        float t = xr[c];
        if (MODE == 1) t += rr[c];
        v[i] = t; s += t; sq += t * t;
    }
    s1[tid] = s; s2[tid] = sq;
    __syncthreads();
    for (int off = 128; off > 0; off >>= 1) {
        if (tid < off) { s1[tid] += s1[tid + off]; s2[tid] += s2[tid + off]; }
        __syncthreads();
    }
    float mu = s1[0] * (1.0f / E);
    float var = s2[0] * (1.0f / E) - mu * mu;
    float rstd = rsqrtf(var + 1e-5f);
    float mkf = mask[row] ? 1.0f : 0.0f;
#pragma unroll
    for (int i = 0; i < 4; i++) {
        int c = tid + i * 256;
        float y = (v[i] - mu) * rstd * g[c] + bb[c];
        float o = (MODE == 0) ? (y * mkf + rr[c]) : (y * mkf);
        if (sizeof(OutT) == 2) ((__half*)out)[(size_t)row * E + c] = __float2half(o);
        else                   ((float*)out)[(size_t)row * E + c] = o;
    }
}

// ------------------------- launch -------------------------------------------
extern "C" void kernel_launch(void* const* d_in, const int* in_sizes, int n_in,
                              void* d_out, int out_size) {
    const float* value = (const float*)d_in[0];
    const float* key   = (const float*)d_in[1];
    const float* query = (const float*)d_in[2];
    const void*  mask_k_raw = d_in[3];
    const void*  mask_q_raw = d_in[4];
    const float* Wv = (const float*)d_in[5];
    const float* Wk = (const float*)d_in[6];
    const float* Wq = (const float*)d_in[7];
    const float* Wo = (const float*)d_in[8];
    const float* ln0_g = (const float*)d_in[9];
    const float* ln0_b = (const float*)d_in[10];
    const float* W1 = (const float*)d_in[11];
    const float* b1 = (const float*)d_in[12];
    const float* W2 = (const float*)d_in[13];
    const float* b2 = (const float*)d_in[14];
    const float* ln1_g = (const float*)d_in[15];
    const float* ln1_b = (const float*)d_in[16];
    float* out = (float*)d_out;

    __half *qh, *kh, *vh, *Wqh, *Wkh, *Wvh, *Woh, *W1h, *W2h;
    __half *qph, *kph, *vph, *attnh, *hh, *g1h;
    float *att, *ff;
    int *mq, *mk;
    cudaGetSymbolAddress((void**)&qh,   g_qh);
    cudaGetSymbolAddress((void**)&kh,   g_kh);
    cudaGetSymbolAddress((void**)&vh,   g_vh);
    cudaGetSymbolAddress((void**)&Wqh,  g_Wqh);
    cudaGetSymbolAddress((void**)&Wkh,  g_Wkh);
    cudaGetSymbolAddress((void**)&Wvh,  g_Wvh);
    cudaGetSymbolAddress((void**)&Woh,  g_Woh);
    cudaGetSymbolAddress((void**)&W1h,  g_W1h);
    cudaGetSymbolAddress((void**)&W2h,  g_W2h);
    cudaGetSymbolAddress((void**)&qph,  g_qph);
    cudaGetSymbolAddress((void**)&kph,  g_kph);
    cudaGetSymbolAddress((void**)&vph,  g_vph);
    cudaGetSymbolAddress((void**)&attnh,g_attnh);
    cudaGetSymbolAddress((void**)&hh,   g_hh);
    cudaGetSymbolAddress((void**)&g1h,  g_g1h);
    cudaGetSymbolAddress((void**)&att,  g_att);
    cudaGetSymbolAddress((void**)&ff,   g_ff);
    cudaGetSymbolAddress((void**)&mq,   g_mq);
    cudaGetSymbolAddress((void**)&mk,   g_mk);

    cudaFuncSetAttribute(tc_gemm<0, __half, true>,  cudaFuncAttributeMaxDynamicSharedMemorySize, GEMM_SMEM_BYTES);
    cudaFuncSetAttribute(tc_gemm<0, float, false>,  cudaFuncAttributeMaxDynamicSharedMemorySize, GEMM_SMEM_BYTES);
    cudaFuncSetAttribute(tc_gemm<1, float, false>,  cudaFuncAttributeMaxDynamicSharedMemorySize, GEMM_SMEM_BYTES);
    cudaFuncSetAttribute(tc_gemm<2, __half, false>, cudaFuncAttributeMaxDynamicSharedMemorySize, GEMM_SMEM_BYTES);

    mask_convert2_kernel<<<1, 256>>>(mask_k_raw, mk, mask_q_raw, mq, NROWS);

    f2h_all_kernel<<<dim3(160, 9), 256>>>(query, qh, key, kh, value, vh,
                                          Wq, Wqh, Wk, Wkh, Wv, Wvh, Wo, Woh,
                                          W1, W1h, W2, W2h);

    dim3 gE3(E / 128, NROWS / 128, 3);
    dim3 gE(E / 128, NROWS / 128);
    dim3 gF(FFDIM / 128, NROWS / 128);

    tc_gemm<0, __half, true><<<gE3, 128, GEMM_SMEM_BYTES>>>(
        qh, Wqh, kh, Wkh, vh, Wvh, nullptr, qph, kph, vph, NROWS, E, E);

    attn_tc_kernel<<<dim3(S / 128, H, B), 128>>>(qph, kph, vph, mq, mk, attnh);

    tc_gemm<0, float, false><<<gE, 128, GEMM_SMEM_BYTES>>>(
        attnh, Woh, nullptr, nullptr, nullptr, nullptr, nullptr,
        att, nullptr, nullptr, NROWS, E, E);

    ln_kernel<0, __half><<<NROWS, 256>>>(att, query, ln0_g, ln0_b, mq, hh);

    tc_gemm<2, __half, false><<<gF, 128, GEMM_SMEM_BYTES>>>(
        hh, W1h, nullptr, nullptr, nullptr, nullptr, b1,
        g1h, nullptr, nullptr, NROWS, FFDIM, E);
    tc_gemm<1, float, false><<<gE, 128, GEMM_SMEM_BYTES>>>(
        g1h, W2h, nullptr, nullptr, nullptr, nullptr, b2,
        ff, nullptr, nullptr, NROWS, E, FFDIM);

    ln_kernel<1, float><<<NROWS, 256>>>(ff, query, ln1_g, ln1_b, mq, out);
}

// round 13
// speedup vs baseline: 1.0212x; 1.0212x over previous
#include <cuda_runtime.h>
#include <cuda_fp16.h>
#include <math.h>

#define E 1024
#define H 16
#define D 64
#define B 4
#define S 1024
#define NROWS (B*S)     // 4096
#define FFDIM 2048
#define ATT_SCALE 0.03125f    // 1/sqrt(1024) = 2^-5 (exact in fp16)

// ------------------------- scratch (no allocations allowed) -----------------
__device__ __half g_qh[NROWS * E];
__device__ __half g_kh[NROWS * E];
__device__ __half g_vh[NROWS * E];
__device__ __half g_Wqh[E * E];
__device__ __half g_Wkh[E * E];
__device__ __half g_Wvh[E * E];
__device__ __half g_Woh[E * E];
__device__ __half g_W1h[E * FFDIM];
__device__ __half g_W2h[FFDIM * E];
__device__ __half g_qph[NROWS * E];
__device__ __half g_kph[NROWS * E];
__device__ __half g_vph[NROWS * E];
__device__ __half g_attnh[NROWS * E];
__device__ float  g_att[NROWS * E];
__device__ __half g_hh[NROWS * E];
__device__ __half g_g1h[NROWS * FFDIM];
__device__ float  g_ff[NROWS * E];
__device__ int    g_mq[NROWS];
__device__ int    g_mk[NROWS];

// ------------------------- mask canonicalization -----------------------------
__device__ __forceinline__ void mask_conv_one(const void* raw, int* out, int n,
                                              int tid, int nthr, int* s_flags) {
    const unsigned char* p = (const unsigned char*)raw;
    int big = 0, nonal = 0;
    for (int i = tid; i < n; i += nthr) {
        unsigned char v = p[i];
        if (v > 1) big = 1;
        if ((i & 3) != 0 && v != 0) nonal = 1;
    }
    if (big)   atomicOr(&s_flags[0], 1);
    if (nonal) atomicOr(&s_flags[1], 1);
    __syncthreads();
    int kind = s_flags[0] ? 2 : (s_flags[1] ? 1 : 0);
    for (int i = tid; i < n; i += nthr) {
        int v;
        if (kind == 2)      v = (((const float*)raw)[i] != 0.0f);
        else if (kind == 1) v = (p[i] != 0);
        else                v = (((const int*)raw)[i] != 0);
        out[i] = v;
    }
}
__global__ void mask_convert2_kernel(const void* __restrict__ rawk, int* __restrict__ outk,
                                     const void* __restrict__ rawq, int* __restrict__ outq,
                                     int n) {
    __shared__ int fk[2], fq[2];
    if (threadIdx.x == 0) { fk[0] = fk[1] = fq[0] = fq[1] = 0; }
    __syncthreads();
    mask_conv_one(rawk, outk, n, threadIdx.x, blockDim.x, fk);
    __syncthreads();
    mask_conv_one(rawq, outq, n, threadIdx.x, blockDim.x, fq);
}

// ------------------------- fused fp32 -> fp16 conversion ---------------------
#define Q_NE (NROWS * E / 4)     // 1048576
#define Q_EE (E * E / 4)         // 262144
#define Q_EF (E * FFDIM / 4)     // 524288

__global__ __launch_bounds__(256)
void f2h_all_kernel(const float* s0, __half* d0, const float* s1, __half* d1,
                    const float* s2, __half* d2, const float* s3, __half* d3,
                    const float* s4, __half* d4, const float* s5, __half* d5,
                    const float* s6, __half* d6, const float* s7, __half* d7,
                    const float* s8, __half* d8) {
    const float* src; __half* dst; int n4;
    switch (blockIdx.y) {
        case 0: src = s0; dst = d0; n4 = Q_NE; break;
        case 1: src = s1; dst = d1; n4 = Q_NE; break;
        case 2: src = s2; dst = d2; n4 = Q_NE; break;
        case 3: src = s3; dst = d3; n4 = Q_EE; break;
        case 4: src = s4; dst = d4; n4 = Q_EE; break;
        case 5: src = s5; dst = d5; n4 = Q_EE; break;
        case 6: src = s6; dst = d6; n4 = Q_EE; break;
        case 7: src = s7; dst = d7; n4 = Q_EF; break;
        default: src = s8; dst = d8; n4 = Q_EF; break;
    }
    int i = blockIdx.x * blockDim.x + threadIdx.x;
    const int stride = gridDim.x * blockDim.x;
    for (; i < n4; i += stride) {
        float4 v = ((const float4*)src)[i];
        __half2* o = (__half2*)dst + 2 * i;
        o[0] = __floats2half2_rn(v.x, v.y);
        o[1] = __floats2half2_rn(v.z, v.w);
    }
}

// ------------------------- mma / ldmatrix helpers ----------------------------
__device__ __forceinline__ unsigned h2u(__half2 h) {
    union { __half2 h; unsigned u; } c; c.h = h; return c.u;
}
__device__ __forceinline__ unsigned u2hm(unsigned u, __half2 s) {
    union { __half2 h; unsigned u; } c; c.u = u;
    c.h = __hmul2(c.h, s);
    return c.u;
}
__device__ __forceinline__ void mma16(float c[4], const unsigned a[4], const unsigned b[2]) {
    asm volatile(
        "mma.sync.aligned.m16n8k16.row.col.f32.f16.f16.f32 "
        "{%0,%1,%2,%3}, {%4,%5,%6,%7}, {%8,%9}, {%0,%1,%2,%3};"
        : "+f"(c[0]), "+f"(c[1]), "+f"(c[2]), "+f"(c[3])
        : "r"(a[0]), "r"(a[1]), "r"(a[2]), "r"(a[3]), "r"(b[0]), "r"(b[1]));
}
__device__ __forceinline__ void ldsm4(unsigned r[4], unsigned saddr) {
    asm volatile("ldmatrix.sync.aligned.m8n8.x4.shared.b16 {%0,%1,%2,%3}, [%4];"
                 : "=r"(r[0]), "=r"(r[1]), "=r"(r[2]), "=r"(r[3]) : "r"(saddr));
}
__device__ __forceinline__ void ldsm4t(unsigned r[4], unsigned saddr) {
    asm volatile("ldmatrix.sync.aligned.m8n8.x4.trans.shared.b16 {%0,%1,%2,%3}, [%4];"
                 : "=r"(r[0]), "=r"(r[1]), "=r"(r[2]), "=r"(r[3]) : "r"(saddr));
}
__device__ __forceinline__ void cp16(void* smem, const void* g) {
    unsigned s = (unsigned)__cvta_generic_to_shared(smem);
    asm volatile("cp.async.cg.shared.global [%0], [%1], 16;\n" :: "r"(s), "l"(g));
}
__device__ __forceinline__ void cp_commit() { asm volatile("cp.async.commit_group;\n"); }
template<int N> __device__ __forceinline__ void cp_wait() {
    asm volatile("cp.async.wait_group %0;\n" :: "n"(N));
}

// ------------------------- fp16 tensor-core GEMM (round 11) ------------------
#define ASTR 40
#define BSTR 136
#define GSTAGES 4
#define STAGE_H (128 * ASTR + 32 * BSTR)           // 9472 halfs per stage
#define GEMM_SMEM_BYTES (GSTAGES * STAGE_H * 2)    // 75776 B

template<int EPI, typename OutT, bool QKV3>
__global__ __launch_bounds__(128, 2)
void tc_gemm(const __half* __restrict__ A0, const __half* __restrict__ B0,
             const __half* __restrict__ A1, const __half* __restrict__ B1,
             const __half* __restrict__ A2, const __half* __restrict__ B2,
             const float* __restrict__ bias, OutT* __restrict__ C0,
             OutT* __restrict__ C1, OutT* __restrict__ C2,
             int M, int N, int K) {
    extern __shared__ __half smem[];
    const __half* A = A0; const __half* Bm = B0; OutT* C = C0;
    if (QKV3) {
        if (blockIdx.z == 1) { A = A1; Bm = B1; C = C1; }
        else if (blockIdx.z == 2) { A = A2; Bm = B2; C = C2; }
    }
    const int tid = threadIdx.x;
    const int bm = blockIdx.y * 128, bn = blockIdx.x * 128;
    const int warp = tid >> 5, lane = tid & 31;
    const int wm = (warp & 1) * 64;
    const int wn = (warp >> 1) * 64;
    const int g = lane >> 2, t4 = lane & 3;
    const int l16 = lane & 15, lhi = (lane & 16) ? 8 : 0;

    const unsigned sbase = (unsigned)__cvta_generic_to_shared(smem);

    float c[4][8][4];
#pragma unroll
    for (int i = 0; i < 4; i++)
#pragma unroll
        for (int j = 0; j < 8; j++)
#pragma unroll
            for (int r = 0; r < 4; r++) c[i][j][r] = 0.0f;

    auto load_stage = [&](int buf, int tI) {
        __half* As = smem + buf * STAGE_H;
        __half* Bs = As + 128 * ASTR;
#pragma unroll
        for (int q = 0; q < 4; q++) {
            int ch = tid + 128 * q;
            int ar = ch >> 2, acc_ = (ch & 3) * 8;
            cp16(&As[ar * ASTR + acc_], A + (size_t)(bm + ar) * K + tI * 32 + acc_);
            int brr = ch >> 4, bcc = (ch & 15) * 8;
            cp16(&Bs[brr * BSTR + bcc], Bm + (size_t)(tI * 32 + brr) * N + bn + bcc);
        }
    };

    const int T = K / 32;
#pragma unroll
    for (int s = 0; s < GSTAGES - 1; s++) {
        load_stage(s, s);
        cp_commit();
    }

    for (int tI = 0; tI < T; tI++) {
        const int buf = tI & (GSTAGES - 1);
        cp_wait<GSTAGES - 2>();
        __syncthreads();
        if (tI + GSTAGES - 1 < T)
            load_stage((tI + GSTAGES - 1) & (GSTAGES - 1), tI + GSTAGES - 1);
        cp_commit();

        const unsigned sA = sbase + 2u * (buf * STAGE_H);
        const unsigned sB = sA + 2u * (128 * ASTR);
#pragma unroll
        for (int step = 0; step < 2; step++) {
            const int k0 = step * 16;
            unsigned af[4][4], bf[8][2];
#pragma unroll
            for (int i = 0; i < 4; i++) {
                unsigned addr = sA + 2u * ((wm + i * 16 + l16) * ASTR + k0 + lhi);
                ldsm4(af[i], addr);
            }
#pragma unroll
            for (int jp = 0; jp < 4; jp++) {
                unsigned addr = sB + 2u * ((k0 + l16) * BSTR + wn + jp * 16 + lhi);
                unsigned r[4];
                ldsm4t(r, addr);
                bf[2 * jp][0] = r[0];     bf[2 * jp][1] = r[1];
                bf[2 * jp + 1][0] = r[2]; bf[2 * jp + 1][1] = r[3];
            }
#pragma unroll
            for (int i = 0; i < 4; i++)
#pragma unroll
                for (int j = 0; j < 8; j++)
                    mma16(c[i][j], af[i], bf[j]);
        }
    }

#pragma unroll
    for (int i = 0; i < 4; i++) {
#pragma unroll
        for (int j = 0; j < 8; j++) {
            const int row0 = bm + wm + i * 16 + g;
            const int col = bn + wn + j * 8 + 2 * t4;
            float v0 = c[i][j][0], v1 = c[i][j][1], v2 = c[i][j][2], v3 = c[i][j][3];
            if (EPI >= 1) {
                float b0 = bias[col], b1 = bias[col + 1];
                v0 += b0; v1 += b1; v2 += b0; v3 += b1;
            }
            if (EPI == 2) {
                v0 *= 1.0f / (1.0f + __expf(-1.702f * v0));
                v1 *= 1.0f / (1.0f + __expf(-1.702f * v1));
                v2 *= 1.0f / (1.0f + __expf(-1.702f * v2));
                v3 *= 1.0f / (1.0f + __expf(-1.702f * v3));
            }
            if (sizeof(OutT) == 2) {
                *(__half2*)((__half*)C + (size_t)row0 * N + col) = __floats2half2_rn(v0, v1);
                *(__half2*)((__half*)C + (size_t)(row0 + 8) * N + col) = __floats2half2_rn(v2, v3);
            } else {
                float2 p0 = {v0, v1}, p1 = {v2, v3};
                *(float2*)((float*)C + (size_t)row0 * N + col) = p0;
                *(float2*)((float*)C + (size_t)(row0 + 8) * N + col) = p1;
            }
        }
    }
}

// ------------------------- fp16 tensor-core flash attention ------------------
// Round-11 shape (KB=32, 19KB smem) + Q pre-scale + launch_bounds(128,3)
// for 3 CTAs/SM.
#define KVSTR 72
#define KB 32

__global__ __launch_bounds__(128, 3)
void attn_tc_kernel(const __half* __restrict__ qp, const __half* __restrict__ kp,
                    const __half* __restrict__ vp, const int* __restrict__ mq,
                    const int* __restrict__ mk, __half* __restrict__ out) {
    __shared__ __half Ks[2][KB * KVSTR];
    __shared__ __half Vs[2][KB * KVSTR];
    __shared__ float kmS[2][KB];

    const int b = blockIdx.z, h = blockIdx.y;
    const int q0 = blockIdx.x * 128;
    const int tid = threadIdx.x;
    const int w = tid >> 5, lane = tid & 31;
    const int g = lane >> 2, t4 = lane & 3;
    const int l16 = lane & 15, lhi = (lane & 16) ? 8 : 0;
    const int l8 = lane & 7, lm = ((lane & 8) ? 8 : 0), ln16 = (lane & 16) ? 8 : 0;

    const unsigned sK0 = (unsigned)__cvta_generic_to_shared(&Ks[0][0]);
    const unsigned sK1 = (unsigned)__cvta_generic_to_shared(&Ks[1][0]);
    const unsigned sV0 = (unsigned)__cvta_generic_to_shared(&Vs[0][0]);
    const unsigned sV1 = (unsigned)__cvta_generic_to_shared(&Vs[1][0]);

    const __half2 qscale = __float2half2_rn(ATT_SCALE);
    unsigned qa[2][4][4];
#pragma unroll
    for (int i = 0; i < 2; i++) {
        const __half* Qr0 = qp + (size_t)(b * S + q0 + w * 32 + i * 16 + g) * E + h * D;
        const __half* Qr1 = Qr0 + (size_t)8 * E;
#pragma unroll
        for (int s = 0; s < 4; s++) {
            qa[i][s][0] = u2hm(*(const unsigned*)&Qr0[16 * s + 2 * t4], qscale);
            qa[i][s][1] = u2hm(*(const unsigned*)&Qr1[16 * s + 2 * t4], qscale);
            qa[i][s][2] = u2hm(*(const unsigned*)&Qr0[16 * s + 8 + 2 * t4], qscale);
            qa[i][s][3] = u2hm(*(const unsigned*)&Qr1[16 * s + 8 + 2 * t4], qscale);
        }
    }

    float oacc[2][8][4];
#pragma unroll
    for (int i = 0; i < 2; i++)
#pragma unroll
        for (int n = 0; n < 8; n++)
#pragma unroll
            for (int r = 0; r < 4; r++) oacc[i][n][r] = 0.0f;
    float lsum[2][2] = {{0.0f, 0.0f}, {0.0f, 0.0f}};

    auto load_tiles = [&](int kt, int buf) {
        int key = tid >> 2, c8 = (tid & 3) * 16;
        const __half* gk = kp + (size_t)(b * S + kt + key) * E + h * D + c8;
        const __half* gv = vp + (size_t)(b * S + kt + key) * E + h * D + c8;
        cp16(&Ks[buf][key * KVSTR + c8], gk);
        cp16(&Ks[buf][key * KVSTR + c8 + 8], gk + 8);
        cp16(&Vs[buf][key * KVSTR + c8], gv);
        cp16(&Vs[buf][key * KVSTR + c8 + 8], gv + 8);
        if (tid < KB) kmS[buf][tid] = mk[b * S + kt + tid] ? 1.0f : 0.0f;
    };

    load_tiles(0, 0);
    cp_commit();

    for (int kb = 0; kb < S / KB; kb++) {
        const int buf = kb & 1;
        if (kb + 1 < S / KB) {
            load_tiles((kb + 1) * KB, buf ^ 1);
            cp_commit();
            cp_wait<1>();
        } else {
            cp_wait<0>();
        }
        __syncthreads();

        const unsigned sK = buf ? sK1 : sK0;
        const unsigned sV = buf ? sV1 : sV0;

        float sc[2][4][4];
#pragma unroll
        for (int i = 0; i < 2; i++)
#pragma unroll
            for (int j = 0; j < 4; j++)
#pragma unroll
                for (int r = 0; r < 4; r++) sc[i][j][r] = 0.0f;
#pragma unroll
        for (int s = 0; s < 4; s++) {
#pragma unroll
            for (int jp = 0; jp < 2; jp++) {
                unsigned addr = sK + 2u * ((jp * 16 + l8 + ln16) * KVSTR + 16 * s + lm);
                unsigned r[4];
                ldsm4(r, addr);
                unsigned bf0[2] = {r[0], r[1]};
                unsigned bf1[2] = {r[2], r[3]};
#pragma unroll
                for (int i = 0; i < 2; i++) {
                    mma16(sc[i][2 * jp], qa[i][s], bf0);
                    mma16(sc[i][2 * jp + 1], qa[i][s], bf1);
                }
            }
        }

        unsigned pp[2][4][2];
#pragma unroll
        for (int i = 0; i < 2; i++) {
#pragma unroll
            for (int j = 0; j < 4; j++) {
                const int c0 = 8 * j + 2 * t4;
                float m0 = kmS[buf][c0], m1 = kmS[buf][c0 + 1];
                float p0 = __expf(sc[i][j][0]) * m0;
                float p1 = __expf(sc[i][j][1]) * m1;
                float p2 = __expf(sc[i][j][2]) * m0;
                float p3 = __expf(sc[i][j][3]) * m1;
                lsum[i][0] += p0 + p1;
                lsum[i][1] += p2 + p3;
                pp[i][j][0] = h2u(__floats2half2_rn(p0, p1));
                pp[i][j][1] = h2u(__floats2half2_rn(p2, p3));
            }
        }

#pragma unroll
        for (int s = 0; s < 2; s++) {
            unsigned pa[2][4];
#pragma unroll
            for (int i = 0; i < 2; i++) {
                pa[i][0] = pp[i][2 * s][0]; pa[i][1] = pp[i][2 * s][1];
                pa[i][2] = pp[i][2 * s + 1][0]; pa[i][3] = pp[i][2 * s + 1][1];
            }
#pragma unroll
            for (int np = 0; np < 4; np++) {
                unsigned addr = sV + 2u * ((16 * s + l16) * KVSTR + np * 16 + lhi);
                unsigned r[4];
                ldsm4t(r, addr);
                unsigned bf0[2] = {r[0], r[1]};
                unsigned bf1[2] = {r[2], r[3]};
#pragma unroll
                for (int i = 0; i < 2; i++) {
                    mma16(oacc[i][2 * np], pa[i], bf0);
                    mma16(oacc[i][2 * np + 1], pa[i], bf1);
                }
            }
        }
        __syncthreads();
    }

#pragma unroll
    for (int i = 0; i < 2; i++) {
        float l0 = lsum[i][0], l1 = lsum[i][1];
        l0 += __shfl_xor_sync(0xffffffffu, l0, 1);
        l0 += __shfl_xor_sync(0xffffffffu, l0, 2);
        l1 += __shfl_xor_sync(0xffffffffu, l1, 1);
        l1 += __shfl_xor_sync(0xffffffffu, l1, 2);

        const int row0 = b * S + q0 + w * 32 + i * 16 + g;
        const float inv0 = mq[row0] ? 1.0f / l0 : 0.0f;
        const float inv1 = mq[row0 + 8] ? 1.0f / l1 : 0.0f;
        __half* o0 = out + (size_t)row0 * E + h * D;
        __half* o1 = o0 + (size_t)8 * E;
#pragma unroll
        for (int n = 0; n < 8; n++) {
            const int c0 = 8 * n + 2 * t4;
            *(__half2*)(o0 + c0) = __floats2half2_rn(oacc[i][n][0] * inv0, oacc[i][n][1] * inv0);
            *(__half2*)(o1 + c0) = __floats2half2_rn(oacc[i][n][2] * inv1, oacc[i][n][3] * inv1);
        }
    }
}

// ------------------------- layernorm + mask + residual -----------------------
template<int MODE, typename OutT>
__global__ __launch_bounds__(256)
void ln_kernel(const float* __restrict__ x, const float* __restrict__ res,
               const float* __restrict__ g, const float* __restrict__ bb,
               const int* __restrict__ mask, OutT* __restrict__ out) {
    __shared__ float s1[256], s2[256];
    const int row = blockIdx.x;
    const int tid = threadIdx.x;
    const float* xr = x + (size_t)row * E;
    const float* rr = res + (size_t)row * E;
    float v[4];
    float s = 0.0f, sq = 0.0f;
#pragma unroll
    for (int i = 0; i < 4; i++) {
        int c = tid + i * 256;
        float t = xr[c];
        if (MODE == 1) t += rr[c];
        v[i] = t; s += t; sq += t * t;
    }
    s1[tid] = s; s2[tid] = sq;
    __syncthreads();
    for (int off = 128; off > 0; off >>= 1) {
        if (tid < off) { s1[tid] += s1[tid + off]; s2[tid] += s2[tid + off]; }
        __syncthreads();
    }
    float mu = s1[0] * (1.0f / E);
    float var = s2[0] * (1.0f / E) - mu * mu;
    float rstd = rsqrtf(var + 1e-5f);
    float mkf = mask[row] ? 1.0f : 0.0f;
#pragma unroll
    for (int i = 0; i < 4; i++) {
        int c = tid + i * 256;
        float y = (v[i] - mu) * rstd * g[c] + bb[c];
        float o = (MODE == 0) ? (y * mkf + rr[c]) : (y * mkf);
        if (sizeof(OutT) == 2) ((__half*)out)[(size_t)row * E + c] = __float2half(o);
        else                   ((float*)out)[(size_t)row * E + c] = o;
    }
}

// ------------------------- launch -------------------------------------------
extern "C" void kernel_launch(void* const* d_in, const int* in_sizes, int n_in,
                              void* d_out, int out_size) {
    const float* value = (const float*)d_in[0];
    const float* key   = (const float*)d_in[1];
    const float* query = (const float*)d_in[2];
    const void*  mask_k_raw = d_in[3];
    const void*  mask_q_raw = d_in[4];
    const float* Wv = (const float*)d_in[5];
    const float* Wk = (const float*)d_in[6];
    const float* Wq = (const float*)d_in[7];
    const float* Wo = (const float*)d_in[8];
    const float* ln0_g = (const float*)d_in[9];
    const float* ln0_b = (const float*)d_in[10];
    const float* W1 = (const float*)d_in[11];
    const float* b1 = (const float*)d_in[12];
    const float* W2 = (const float*)d_in[13];
    const float* b2 = (const float*)d_in[14];
    const float* ln1_g = (const float*)d_in[15];
    const float* ln1_b = (const float*)d_in[16];
    float* out = (float*)d_out;

    __half *qh, *kh, *vh, *Wqh, *Wkh, *Wvh, *Woh, *W1h, *W2h;
    __half *qph, *kph, *vph, *attnh, *hh, *g1h;
    float *att, *ff;
    int *mq, *mk;
    cudaGetSymbolAddress((void**)&qh,   g_qh);
    cudaGetSymbolAddress((void**)&kh,   g_kh);
    cudaGetSymbolAddress((void**)&vh,   g_vh);
    cudaGetSymbolAddress((void**)&Wqh,  g_Wqh);
    cudaGetSymbolAddress((void**)&Wkh,  g_Wkh);
    cudaGetSymbolAddress((void**)&Wvh,  g_Wvh);
    cudaGetSymbolAddress((void**)&Woh,  g_Woh);
    cudaGetSymbolAddress((void**)&W1h,  g_W1h);
    cudaGetSymbolAddress((void**)&W2h,  g_W2h);
    cudaGetSymbolAddress((void**)&qph,  g_qph);
    cudaGetSymbolAddress((void**)&kph,  g_kph);
    cudaGetSymbolAddress((void**)&vph,  g_vph);
    cudaGetSymbolAddress((void**)&attnh,g_attnh);
    cudaGetSymbolAddress((void**)&hh,   g_hh);
    cudaGetSymbolAddress((void**)&g1h,  g_g1h);
    cudaGetSymbolAddress((void**)&att,  g_att);
    cudaGetSymbolAddress((void**)&ff,   g_ff);
    cudaGetSymbolAddress((void**)&mq,   g_mq);
    cudaGetSymbolAddress((void**)&mk,   g_mk);

    cudaFuncSetAttribute(tc_gemm<0, __half, true>,  cudaFuncAttributeMaxDynamicSharedMemorySize, GEMM_SMEM_BYTES);
    cudaFuncSetAttribute(tc_gemm<0, float, false>,  cudaFuncAttributeMaxDynamicSharedMemorySize, GEMM_SMEM_BYTES);
    cudaFuncSetAttribute(tc_gemm<1, float, false>,  cudaFuncAttributeMaxDynamicSharedMemorySize, GEMM_SMEM_BYTES);
    cudaFuncSetAttribute(tc_gemm<2, __half, false>, cudaFuncAttributeMaxDynamicSharedMemorySize, GEMM_SMEM_BYTES);

    mask_convert2_kernel<<<1, 256>>>(mask_k_raw, mk, mask_q_raw, mq, NROWS);

    f2h_all_kernel<<<dim3(160, 9), 256>>>(query, qh, key, kh, value, vh,
                                          Wq, Wqh, Wk, Wkh, Wv, Wvh, Wo, Woh,
                                          W1, W1h, W2, W2h);

    dim3 gE3(E / 128, NROWS / 128, 3);
    dim3 gE(E / 128, NROWS / 128);
    dim3 gF(FFDIM / 128, NROWS / 128);

    tc_gemm<0, __half, true><<<gE3, 128, GEMM_SMEM_BYTES>>>(
        qh, Wqh, kh, Wkh, vh, Wvh, nullptr, qph, kph, vph, NROWS, E, E);

    attn_tc_kernel<<<dim3(S / 128, H, B), 128>>>(qph, kph, vph, mq, mk, attnh);

    tc_gemm<0, float, false><<<gE, 128, GEMM_SMEM_BYTES>>>(
        attnh, Woh, nullptr, nullptr, nullptr, nullptr, nullptr,
        att, nullptr, nullptr, NROWS, E, E);

    ln_kernel<0, __half><<<NROWS, 256>>>(att, query, ln0_g, ln0_b, mq, hh);

    tc_gemm<2, __half, false><<<gF, 128, GEMM_SMEM_BYTES>>>(
        hh, W1h, nullptr, nullptr, nullptr, nullptr, b1,
        g1h, nullptr, nullptr, NROWS, FFDIM, E);
    tc_gemm<1, float, false><<<gE, 128, GEMM_SMEM_BYTES>>>(
        g1h, W2h, nullptr, nullptr, nullptr, nullptr, b2,
        ff, nullptr, nullptr, NROWS, E, FFDIM);

    ln_kernel<1, float><<<NROWS, 256>>>(ff, query, ln1_g, ln1_b, mq, out);
}

// round 15
// speedup vs baseline: 1.1267x; 1.1033x over previous
#include <cuda_runtime.h>
#include <cuda_fp16.h>
#include <math.h>

#define E 1024
#define H 16
#define D 64
#define B 4
#define S 1024
#define NROWS (B*S)     // 4096
#define FFDIM 2048
#define ATT_SCALE 0.03125f    // 1/sqrt(1024) = 2^-5 (exact in fp16)

// ------------------------- scratch (no allocations allowed) -----------------
__device__ __half g_qh[NROWS * E];
__device__ __half g_kh[NROWS * E];
__device__ __half g_vh[NROWS * E];
__device__ __half g_Wqh[E * E];
__device__ __half g_Wkh[E * E];
__device__ __half g_Wvh[E * E];
__device__ __half g_Woh[E * E];
__device__ __half g_W1h[E * FFDIM];
__device__ __half g_W2h[FFDIM * E];
__device__ __half g_qph[NROWS * E];
__device__ __half g_kph[NROWS * E];
__device__ __half g_vph[NROWS * E];
__device__ __half g_qg[NROWS * E];      // compacted active q rows
__device__ __half g_kg[NROWS * E];      // compacted active k rows (zero padded)
__device__ __half g_vg[NROWS * E];
__device__ __half g_attnh[NROWS * E];
__device__ float  g_att[NROWS * E];
__device__ __half g_hh[NROWS * E];
__device__ __half g_g1h[NROWS * FFDIM];
__device__ float  g_ff[NROWS * E];
__device__ int    g_mq[NROWS];
__device__ int    g_mk[NROWS];
__device__ int    g_qidx[NROWS];        // per-batch compact slot -> row (-1 pad)
__device__ int    g_kidx[NROWS];
__device__ int    g_cntq[B];
__device__ int    g_cntk[B];

// ------------------------- mask canonicalization -----------------------------
__device__ __forceinline__ void mask_conv_one(const void* raw, int* out, int n,
                                              int tid, int nthr, int* s_flags) {
    const unsigned char* p = (const unsigned char*)raw;
    int big = 0, nonal = 0;
    for (int i = tid; i < n; i += nthr) {
        unsigned char v = p[i];
        if (v > 1) big = 1;
        if ((i & 3) != 0 && v != 0) nonal = 1;
    }
    if (big)   atomicOr(&s_flags[0], 1);
    if (nonal) atomicOr(&s_flags[1], 1);
    __syncthreads();
    int kind = s_flags[0] ? 2 : (s_flags[1] ? 1 : 0);
    for (int i = tid; i < n; i += nthr) {
        int v;
        if (kind == 2)      v = (((const float*)raw)[i] != 0.0f);
        else if (kind == 1) v = (p[i] != 0);
        else                v = (((const int*)raw)[i] != 0);
        out[i] = v;
    }
}
__global__ void mask_convert2_kernel(const void* __restrict__ rawk, int* __restrict__ outk,
                                     const void* __restrict__ rawq, int* __restrict__ outq,
                                     int n) {
    __shared__ int fk[2], fq[2];
    if (threadIdx.x == 0) { fk[0] = fk[1] = fq[0] = fq[1] = 0; }
    __syncthreads();
    mask_conv_one(rawk, outk, n, threadIdx.x, blockDim.x, fk);
    __syncthreads();
    mask_conv_one(rawq, outq, n, threadIdx.x, blockDim.x, fq);
}

// ------------------------- index build (stable prefix scan) ------------------
__global__ __launch_bounds__(1024)
void build_index_kernel(const int* __restrict__ mq, const int* __restrict__ mk,
                        int* __restrict__ qidx, int* __restrict__ kidx,
                        int* __restrict__ cntq, int* __restrict__ cntk) {
    __shared__ int sh[1024];
    const int b = blockIdx.x, t = threadIdx.x;
    // --- q ---
    int flag = mq[b * S + t];
    sh[t] = flag; __syncthreads();
    for (int off = 1; off < 1024; off <<= 1) {
        int v = (t >= off) ? sh[t - off] : 0;
        __syncthreads();
        sh[t] += v;
        __syncthreads();
    }
    int total = sh[1023];
    int excl = sh[t] - flag;
    if (flag) qidx[b * S + excl] = t;
    if (t >= total) qidx[b * S + t] = -1;
    if (t == 0) cntq[b] = total;
    __syncthreads();
    // --- k ---
    flag = mk[b * S + t];
    sh[t] = flag; __syncthreads();
    for (int off = 1; off < 1024; off <<= 1) {
        int v = (t >= off) ? sh[t - off] : 0;
        __syncthreads();
        sh[t] += v;
        __syncthreads();
    }
    total = sh[1023];
    excl = sh[t] - flag;
    if (flag) kidx[b * S + excl] = t;
    if (t >= total) kidx[b * S + t] = -1;
    if (t == 0) cntk[b] = total;
}

// ------------------------- gather active rows --------------------------------
// blockIdx.y: 0=q(qidx), 1=k(kidx), 2=v(kidx). One warp per compact row.
// Row = E halfs = 2048 bytes = 128 uint4 -> 4 uint4 per lane.
__global__ __launch_bounds__(256)
void gather_kernel(const __half* __restrict__ qp, const __half* __restrict__ kp,
                   const __half* __restrict__ vp,
                   const int* __restrict__ qidx, const int* __restrict__ kidx,
                   __half* __restrict__ qg, __half* __restrict__ kg,
                   __half* __restrict__ vg) {
    const int warp = threadIdx.x >> 5, lane = threadIdx.x & 31;
    const int r = blockIdx.x * 8 + warp;         // compact slot (global)
    const int b = r >> 10;
    const __half* src;  __half* dst;  int row;
    if (blockIdx.y == 0) { row = qidx[r]; src = qp; dst = qg; }
    else if (blockIdx.y == 1) { row = kidx[r]; src = kp; dst = kg; }
    else { row = kidx[r]; src = vp; dst = vg; }
    uint4* d = (uint4*)(dst + (size_t)r * E);
    if (row >= 0) {
        const uint4* s = (const uint4*)(src + (size_t)(b * S + row) * E);
        d[lane] = s[lane];
        d[lane + 32] = s[lane + 32];
        d[lane + 64] = s[lane + 64];
        d[lane + 96] = s[lane + 96];
    } else {
        uint4 z = {0, 0, 0, 0};
        d[lane] = z;
        d[lane + 32] = z;
        d[lane + 64] = z;
        d[lane + 96] = z;
    }
}

// ------------------------- fused fp32 -> fp16 conversion ---------------------
#define Q_NE (NROWS * E / 4)     // 1048576
#define Q_EE (E * E / 4)         // 262144
#define Q_EF (E * FFDIM / 4)     // 524288

__global__ __launch_bounds__(256)
void f2h_all_kernel(const float* s0, __half* d0, const float* s1, __half* d1,
                    const float* s2, __half* d2, const float* s3, __half* d3,
                    const float* s4, __half* d4, const float* s5, __half* d5,
                    const float* s6, __half* d6, const float* s7, __half* d7,
                    const float* s8, __half* d8) {
    const float* src; __half* dst; int n4;
    switch (blockIdx.y) {
        case 0: src = s0; dst = d0; n4 = Q_NE; break;
        case 1: src = s1; dst = d1; n4 = Q_NE; break;
        case 2: src = s2; dst = d2; n4 = Q_NE; break;
        case 3: src = s3; dst = d3; n4 = Q_EE; break;
        case 4: src = s4; dst = d4; n4 = Q_EE; break;
        case 5: src = s5; dst = d5; n4 = Q_EE; break;
        case 6: src = s6; dst = d6; n4 = Q_EE; break;
        case 7: src = s7; dst = d7; n4 = Q_EF; break;
        default: src = s8; dst = d8; n4 = Q_EF; break;
    }
    int i = blockIdx.x * blockDim.x + threadIdx.x;
    const int stride = gridDim.x * blockDim.x;
    for (; i < n4; i += stride) {
        float4 v = ((const float4*)src)[i];
        __half2* o = (__half2*)dst + 2 * i;
        o[0] = __floats2half2_rn(v.x, v.y);
        o[1] = __floats2half2_rn(v.z, v.w);
    }
}

// ------------------------- mma / ldmatrix helpers ----------------------------
__device__ __forceinline__ unsigned h2u(__half2 h) {
    union { __half2 h; unsigned u; } c; c.h = h; return c.u;
}
__device__ __forceinline__ unsigned u2hm(unsigned u, __half2 s) {
    union { __half2 h; unsigned u; } c; c.u = u;
    c.h = __hmul2(c.h, s);
    return c.u;
}
__device__ __forceinline__ void mma16(float c[4], const unsigned a[4], const unsigned b[2]) {
    asm volatile(
        "mma.sync.aligned.m16n8k16.row.col.f32.f16.f16.f32 "
        "{%0,%1,%2,%3}, {%4,%5,%6,%7}, {%8,%9}, {%0,%1,%2,%3};"
        : "+f"(c[0]), "+f"(c[1]), "+f"(c[2]), "+f"(c[3])
        : "r"(a[0]), "r"(a[1]), "r"(a[2]), "r"(a[3]), "r"(b[0]), "r"(b[1]));
}
__device__ __forceinline__ void ldsm4(unsigned r[4], unsigned saddr) {
    asm volatile("ldmatrix.sync.aligned.m8n8.x4.shared.b16 {%0,%1,%2,%3}, [%4];"
                 : "=r"(r[0]), "=r"(r[1]), "=r"(r[2]), "=r"(r[3]) : "r"(saddr));
}
__device__ __forceinline__ void ldsm4t(unsigned r[4], unsigned saddr) {
    asm volatile("ldmatrix.sync.aligned.m8n8.x4.trans.shared.b16 {%0,%1,%2,%3}, [%4];"
                 : "=r"(r[0]), "=r"(r[1]), "=r"(r[2]), "=r"(r[3]) : "r"(saddr));
}
__device__ __forceinline__ void cp16(void* smem, const void* g) {
    unsigned s = (unsigned)__cvta_generic_to_shared(smem);
    asm volatile("cp.async.cg.shared.global [%0], [%1], 16;\n" :: "r"(s), "l"(g));
}
__device__ __forceinline__ void cp_commit() { asm volatile("cp.async.commit_group;\n"); }
template<int N> __device__ __forceinline__ void cp_wait() {
    asm volatile("cp.async.wait_group %0;\n" :: "n"(N));
}

// ------------------------- fp16 tensor-core GEMM (round 11) ------------------
#define ASTR 40
#define BSTR 136
#define GSTAGES 4
#define STAGE_H (128 * ASTR + 32 * BSTR)           // 9472 halfs per stage
#define GEMM_SMEM_BYTES (GSTAGES * STAGE_H * 2)    // 75776 B

template<int EPI, typename OutT, bool QKV3>
__global__ __launch_bounds__(128, 2)
void tc_gemm(const __half* __restrict__ A0, const __half* __restrict__ B0,
             const __half* __restrict__ A1, const __half* __restrict__ B1,
             const __half* __restrict__ A2, const __half* __restrict__ B2,
             const float* __restrict__ bias, OutT* __restrict__ C0,
             OutT* __restrict__ C1, OutT* __restrict__ C2,
             int M, int N, int K) {
    extern __shared__ __half smem[];
    const __half* A = A0; const __half* Bm = B0; OutT* C = C0;
    if (QKV3) {
        if (blockIdx.z == 1) { A = A1; Bm = B1; C = C1; }
        else if (blockIdx.z == 2) { A = A2; Bm = B2; C = C2; }
    }
    const int tid = threadIdx.x;
    const int bm = blockIdx.y * 128, bn = blockIdx.x * 128;
    const int warp = tid >> 5, lane = tid & 31;
    const int wm = (warp & 1) * 64;
    const int wn = (warp >> 1) * 64;
    const int g = lane >> 2, t4 = lane & 3;
    const int l16 = lane & 15, lhi = (lane & 16) ? 8 : 0;

    const unsigned sbase = (unsigned)__cvta_generic_to_shared(smem);

    float c[4][8][4];
#pragma unroll
    for (int i = 0; i < 4; i++)
#pragma unroll
        for (int j = 0; j < 8; j++)
#pragma unroll
            for (int r = 0; r < 4; r++) c[i][j][r] = 0.0f;

    auto load_stage = [&](int buf, int tI) {
        __half* As = smem + buf * STAGE_H;
        __half* Bs = As + 128 * ASTR;
#pragma unroll
        for (int q = 0; q < 4; q++) {
            int ch = tid + 128 * q;
            int ar = ch >> 2, acc_ = (ch & 3) * 8;
            cp16(&As[ar * ASTR + acc_], A + (size_t)(bm + ar) * K + tI * 32 + acc_);
            int brr = ch >> 4, bcc = (ch & 15) * 8;
            cp16(&Bs[brr * BSTR + bcc], Bm + (size_t)(tI * 32 + brr) * N + bn + bcc);
        }
    };

    const int T = K / 32;
#pragma unroll
    for (int s = 0; s < GSTAGES - 1; s++) {
        load_stage(s, s);
        cp_commit();
    }

    for (int tI = 0; tI < T; tI++) {
        const int buf = tI & (GSTAGES - 1);
        cp_wait<GSTAGES - 2>();
        __syncthreads();
        if (tI + GSTAGES - 1 < T)
            load_stage((tI + GSTAGES - 1) & (GSTAGES - 1), tI + GSTAGES - 1);
        cp_commit();

        const unsigned sA = sbase + 2u * (buf * STAGE_H);
        const unsigned sB = sA + 2u * (128 * ASTR);
#pragma unroll
        for (int step = 0; step < 2; step++) {
            const int k0 = step * 16;
            unsigned af[4][4], bf[8][2];
#pragma unroll
            for (int i = 0; i < 4; i++) {
                unsigned addr = sA + 2u * ((wm + i * 16 + l16) * ASTR + k0 + lhi);
                ldsm4(af[i], addr);
            }
#pragma unroll
            for (int jp = 0; jp < 4; jp++) {
                unsigned addr = sB + 2u * ((k0 + l16) * BSTR + wn + jp * 16 + lhi);
                unsigned r[4];
                ldsm4t(r, addr);
                bf[2 * jp][0] = r[0];     bf[2 * jp][1] = r[1];
                bf[2 * jp + 1][0] = r[2]; bf[2 * jp + 1][1] = r[3];
            }
#pragma unroll
            for (int i = 0; i < 4; i++)
#pragma unroll
                for (int j = 0; j < 8; j++)
                    mma16(c[i][j], af[i], bf[j]);
        }
    }

#pragma unroll
    for (int i = 0; i < 4; i++) {
#pragma unroll
        for (int j = 0; j < 8; j++) {
            const int row0 = bm + wm + i * 16 + g;
            const int col = bn + wn + j * 8 + 2 * t4;
            float v0 = c[i][j][0], v1 = c[i][j][1], v2 = c[i][j][2], v3 = c[i][j][3];
            if (EPI >= 1) {
                float b0 = bias[col], b1 = bias[col + 1];
                v0 += b0; v1 += b1; v2 += b0; v3 += b1;
            }
            if (EPI == 2) {
                v0 *= 1.0f / (1.0f + __expf(-1.702f * v0));
                v1 *= 1.0f / (1.0f + __expf(-1.702f * v1));
                v2 *= 1.0f / (1.0f + __expf(-1.702f * v2));
                v3 *= 1.0f / (1.0f + __expf(-1.702f * v3));
            }
            if (sizeof(OutT) == 2) {
                *(__half2*)((__half*)C + (size_t)row0 * N + col) = __floats2half2_rn(v0, v1);
                *(__half2*)((__half*)C + (size_t)(row0 + 8) * N + col) = __floats2half2_rn(v2, v3);
            } else {
                float2 p0 = {v0, v1}, p1 = {v2, v3};
                *(float2*)((float*)C + (size_t)row0 * N + col) = p0;
                *(float2*)((float*)C + (size_t)(row0 + 8) * N + col) = p1;
            }
        }
    }
}

// ------------------------- compacted fp16 flash attention --------------------
#define KVSTR 72
#define KB 32

__global__ __launch_bounds__(128, 3)
void attn_tc_kernel(const __half* __restrict__ qg, const __half* __restrict__ kg,
                    const __half* __restrict__ vg, const int* __restrict__ qidx,
                    const int* __restrict__ cntq_a, const int* __restrict__ cntk_a,
                    __half* __restrict__ out) {
    __shared__ __half Ks[2][KB * KVSTR];
    __shared__ __half Vs[2][KB * KVSTR];

    const int b = blockIdx.z, h = blockIdx.y;
    const int q0 = blockIdx.x * 128;
    const int cntq = cntq_a[b];
    if (q0 >= cntq) return;                 // uniform early exit
    const int cntk = cntk_a[b];
    const int nkt = (cntk + KB - 1) / KB;

    const int tid = threadIdx.x;
    const int w = tid >> 5, lane = tid & 31;
    const int g = lane >> 2, t4 = lane & 3;
    const int l16 = lane & 15, lhi = (lane & 16) ? 8 : 0;
    const int l8 = lane & 7, lm = ((lane & 8) ? 8 : 0), ln16 = (lane & 16) ? 8 : 0;

    const unsigned sK0 = (unsigned)__cvta_generic_to_shared(&Ks[0][0]);
    const unsigned sK1 = (unsigned)__cvta_generic_to_shared(&Ks[1][0]);
    const unsigned sV0 = (unsigned)__cvta_generic_to_shared(&Vs[0][0]);
    const unsigned sV1 = (unsigned)__cvta_generic_to_shared(&Vs[1][0]);

    const __half2 qscale = __float2half2_rn(ATT_SCALE);
    unsigned qa[2][4][4];
#pragma unroll
    for (int i = 0; i < 2; i++) {
        const __half* Qr0 = qg + (size_t)(b * S + q0 + w * 32 + i * 16 + g) * E + h * D;
        const __half* Qr1 = Qr0 + (size_t)8 * E;
#pragma unroll
        for (int s = 0; s < 4; s++) {
            qa[i][s][0] = u2hm(*(const unsigned*)&Qr0[16 * s + 2 * t4], qscale);
            qa[i][s][1] = u2hm(*(const unsigned*)&Qr1[16 * s + 2 * t4], qscale);
            qa[i][s][2] = u2hm(*(const unsigned*)&Qr0[16 * s + 8 + 2 * t4], qscale);
            qa[i][s][3] = u2hm(*(const unsigned*)&Qr1[16 * s + 8 + 2 * t4], qscale);
        }
    }

    float oacc[2][8][4];
#pragma unroll
    for (int i = 0; i < 2; i++)
#pragma unroll
        for (int n = 0; n < 8; n++)
#pragma unroll
            for (int r = 0; r < 4; r++) oacc[i][n][r] = 0.0f;
    float lsum[2][2] = {{0.0f, 0.0f}, {0.0f, 0.0f}};

    auto load_tiles = [&](int kt, int buf) {
        int key = tid >> 2, c8 = (tid & 3) * 16;
        const __half* gk = kg + (size_t)(b * S + kt + key) * E + h * D + c8;
        const __half* gv = vg + (size_t)(b * S + kt + key) * E + h * D + c8;
        cp16(&Ks[buf][key * KVSTR + c8], gk);
        cp16(&Ks[buf][key * KVSTR + c8 + 8], gk + 8);
        cp16(&Vs[buf][key * KVSTR + c8], gv);
        cp16(&Vs[buf][key * KVSTR + c8 + 8], gv + 8);
    };

    load_tiles(0, 0);
    cp_commit();

    for (int kb = 0; kb < nkt; kb++) {
        const int buf = kb & 1;
        if (kb + 1 < nkt) {
            load_tiles((kb + 1) * KB, buf ^ 1);
            cp_commit();
            cp_wait<1>();
        } else {
            cp_wait<0>();
        }
        __syncthreads();

        const unsigned sK = buf ? sK1 : sK0;
        const unsigned sV = buf ? sV1 : sV0;

        float sc[2][4][4];
#pragma unroll
        for (int i = 0; i < 2; i++)
#pragma unroll
            for (int j = 0; j < 4; j++)
#pragma unroll
                for (int r = 0; r < 4; r++) sc[i][j][r] = 0.0f;
#pragma unroll
        for (int s = 0; s < 4; s++) {
#pragma unroll
            for (int jp = 0; jp < 2; jp++) {
                unsigned addr = sK + 2u * ((jp * 16 + l8 + ln16) * KVSTR + 16 * s + lm);
                unsigned r[4];
                ldsm4(r, addr);
                unsigned bf0[2] = {r[0], r[1]};
                unsigned bf1[2] = {r[2], r[3]};
#pragma unroll
                for (int i = 0; i < 2; i++) {
                    mma16(sc[i][2 * jp], qa[i][s], bf0);
                    mma16(sc[i][2 * jp + 1], qa[i][s], bf1);
                }
            }
        }

        const int kbase = kb * KB;
        unsigned pp[2][4][2];
#pragma unroll
        for (int i = 0; i < 2; i++) {
#pragma unroll
            for (int j = 0; j < 4; j++) {
                const int c0 = 8 * j + 2 * t4;
                float m0 = (kbase + c0 < cntk) ? 1.0f : 0.0f;
                float m1 = (kbase + c0 + 1 < cntk) ? 1.0f : 0.0f;
                float p0 = __expf(sc[i][j][0]) * m0;
                float p1 = __expf(sc[i][j][1]) * m1;
                float p2 = __expf(sc[i][j][2]) * m0;
                float p3 = __expf(sc[i][j][3]) * m1;
                lsum[i][0] += p0 + p1;
                lsum[i][1] += p2 + p3;
                pp[i][j][0] = h2u(__floats2half2_rn(p0, p1));
                pp[i][j][1] = h2u(__floats2half2_rn(p2, p3));
            }
        }

#pragma unroll
        for (int s = 0; s < 2; s++) {
            unsigned pa[2][4];
#pragma unroll
            for (int i = 0; i < 2; i++) {
                pa[i][0] = pp[i][2 * s][0]; pa[i][1] = pp[i][2 * s][1];
                pa[i][2] = pp[i][2 * s + 1][0]; pa[i][3] = pp[i][2 * s + 1][1];
            }
#pragma unroll
            for (int np = 0; np < 4; np++) {
                unsigned addr = sV + 2u * ((16 * s + l16) * KVSTR + np * 16 + lhi);
                unsigned r[4];
                ldsm4t(r, addr);
                unsigned bf0[2] = {r[0], r[1]};
                unsigned bf1[2] = {r[2], r[3]};
#pragma unroll
                for (int i = 0; i < 2; i++) {
                    mma16(oacc[i][2 * np], pa[i], bf0);
                    mma16(oacc[i][2 * np + 1], pa[i], bf1);
                }
            }
        }
        __syncthreads();
    }

#pragma unroll
    for (int i = 0; i < 2; i++) {
        float l0 = lsum[i][0], l1 = lsum[i][1];
        l0 += __shfl_xor_sync(0xffffffffu, l0, 1);
        l0 += __shfl_xor_sync(0xffffffffu, l0, 2);
        l1 += __shfl_xor_sync(0xffffffffu, l1, 1);
        l1 += __shfl_xor_sync(0xffffffffu, l1, 2);

        const int slot0 = q0 + w * 32 + i * 16 + g;
        const int idx0 = qidx[b * S + slot0];
        const int idx1 = qidx[b * S + slot0 + 8];
        const float inv0 = 1.0f / l0;
        const float inv1 = 1.0f / l1;
        if (idx0 >= 0) {
            __half* o0 = out + (size_t)(b * S + idx0) * E + h * D;
#pragma unroll
            for (int n = 0; n < 8; n++) {
                const int c0 = 8 * n + 2 * t4;
                *(__half2*)(o0 + c0) = __floats2half2_rn(oacc[i][n][0] * inv0, oacc[i][n][1] * inv0);
            }
        }
        if (idx1 >= 0) {
            __half* o1 = out + (size_t)(b * S + idx1) * E + h * D;
#pragma unroll
            for (int n = 0; n < 8; n++) {
                const int c0 = 8 * n + 2 * t4;
                *(__half2*)(o1 + c0) = __floats2half2_rn(oacc[i][n][2] * inv1, oacc[i][n][3] * inv1);
            }
        }
    }
}

// ------------------------- layernorm + mask + residual -----------------------
template<int MODE, typename OutT>
__global__ __launch_bounds__(256)
void ln_kernel(const float* __restrict__ x, const float* __restrict__ res,
               const float* __restrict__ g, const float* __restrict__ bb,
               const int* __restrict__ mask, OutT* __restrict__ out) {
    __shared__ float s1[256], s2[256];
    const int row = blockIdx.x;
    const int tid = threadIdx.x;
    const float* xr = x + (size_t)row * E;
    const float* rr = res + (size_t)row * E;
    float v[4];
    float s = 0.0f, sq = 0.0f;
#pragma unroll
    for (int i = 0; i < 4; i++) {
        int c = tid + i * 256;
        float t = xr[c];
        if (MODE == 1) t += rr[c];
        v[i] = t; s += t; sq += t * t;
    }
    s1[tid] = s; s2[tid] = sq;
    __syncthreads();
    for (int off = 128; off > 0; off >>= 1) {
        if (tid < off) { s1[tid] += s1[tid + off]; s2[tid] += s2[tid + off]; }
        __syncthreads();
    }
    float mu = s1[0] * (1.0f / E);
    float var = s2[0] * (1.0f / E) - mu * mu;
    float rstd = rsqrtf(var + 1e-5f);
    float mkf = mask[row] ? 1.0f : 0.0f;
#pragma unroll
    for (int i = 0; i < 4; i++) {
        int c = tid + i * 256;
        float y = (v[i] - mu) * rstd * g[c] + bb[c];
        float o = (MODE == 0) ? (y * mkf + rr[c]) : (y * mkf);
        if (sizeof(OutT) == 2) ((__half*)out)[(size_t)row * E + c] = __float2half(o);
        else                   ((float*)out)[(size_t)row * E + c] = o;
    }
}

// ------------------------- launch -------------------------------------------
extern "C" void kernel_launch(void* const* d_in, const int* in_sizes, int n_in,
                              void* d_out, int out_size) {
    const float* value = (const float*)d_in[0];
    const float* key   = (const float*)d_in[1];
    const float* query = (const float*)d_in[2];
    const void*  mask_k_raw = d_in[3];
    const void*  mask_q_raw = d_in[4];
    const float* Wv = (const float*)d_in[5];
    const float* Wk = (const float*)d_in[6];
    const float* Wq = (const float*)d_in[7];
    const float* Wo = (const float*)d_in[8];
    const float* ln0_g = (const float*)d_in[9];
    const float* ln0_b = (const float*)d_in[10];
    const float* W1 = (const float*)d_in[11];
    const float* b1 = (const float*)d_in[12];
    const float* W2 = (const float*)d_in[13];
    const float* b2 = (const float*)d_in[14];
    const float* ln1_g = (const float*)d_in[15];
    const float* ln1_b = (const float*)d_in[16];
    float* out = (float*)d_out;

    __half *qh, *kh, *vh, *Wqh, *Wkh, *Wvh, *Woh, *W1h, *W2h;
    __half *qph, *kph, *vph, *qg, *kg, *vg, *attnh, *hh, *g1h;
    float *att, *ff;
    int *mq, *mk, *qidx, *kidx, *cntq, *cntk;
    cudaGetSymbolAddress((void**)&qh,   g_qh);
    cudaGetSymbolAddress((void**)&kh,   g_kh);
    cudaGetSymbolAddress((void**)&vh,   g_vh);
    cudaGetSymbolAddress((void**)&Wqh,  g_Wqh);
    cudaGetSymbolAddress((void**)&Wkh,  g_Wkh);
    cudaGetSymbolAddress((void**)&Wvh,  g_Wvh);
    cudaGetSymbolAddress((void**)&Woh,  g_Woh);
    cudaGetSymbolAddress((void**)&W1h,  g_W1h);
    cudaGetSymbolAddress((void**)&W2h,  g_W2h);
    cudaGetSymbolAddress((void**)&qph,  g_qph);
    cudaGetSymbolAddress((void**)&kph,  g_kph);
    cudaGetSymbolAddress((void**)&vph,  g_vph);
    cudaGetSymbolAddress((void**)&qg,   g_qg);
    cudaGetSymbolAddress((void**)&kg,   g_kg);
    cudaGetSymbolAddress((void**)&vg,   g_vg);
    cudaGetSymbolAddress((void**)&attnh,g_attnh);
    cudaGetSymbolAddress((void**)&hh,   g_hh);
    cudaGetSymbolAddress((void**)&g1h,  g_g1h);
    cudaGetSymbolAddress((void**)&att,  g_att);
    cudaGetSymbolAddress((void**)&ff,   g_ff);
    cudaGetSymbolAddress((void**)&mq,   g_mq);
    cudaGetSymbolAddress((void**)&mk,   g_mk);
    cudaGetSymbolAddress((void**)&qidx, g_qidx);
    cudaGetSymbolAddress((void**)&kidx, g_kidx);
    cudaGetSymbolAddress((void**)&cntq, g_cntq);
    cudaGetSymbolAddress((void**)&cntk, g_cntk);

    cudaFuncSetAttribute(tc_gemm<0, __half, true>,  cudaFuncAttributeMaxDynamicSharedMemorySize, GEMM_SMEM_BYTES);
    cudaFuncSetAttribute(tc_gemm<0, float, false>,  cudaFuncAttributeMaxDynamicSharedMemorySize, GEMM_SMEM_BYTES);
    cudaFuncSetAttribute(tc_gemm<1, float, false>,  cudaFuncAttributeMaxDynamicSharedMemorySize, GEMM_SMEM_BYTES);
    cudaFuncSetAttribute(tc_gemm<2, __half, false>, cudaFuncAttributeMaxDynamicSharedMemorySize, GEMM_SMEM_BYTES);

    mask_convert2_kernel<<<1, 256>>>(mask_k_raw, mk, mask_q_raw, mq, NROWS);
    build_index_kernel<<<B, 1024>>>(mq, mk, qidx, kidx, cntq, cntk);

    f2h_all_kernel<<<dim3(160, 9), 256>>>(query, qh, key, kh, value, vh,
                                          Wq, Wqh, Wk, Wkh, Wv, Wvh, Wo, Woh,
                                          W1, W1h, W2, W2h);

    dim3 gE3(E / 128, NROWS / 128, 3);
    dim3 gE(E / 128, NROWS / 128);
    dim3 gF(FFDIM / 128, NROWS / 128);

    tc_gemm<0, __half, true><<<gE3, 128, GEMM_SMEM_BYTES>>>(
        qh, Wqh, kh, Wkh, vh, Wvh, nullptr, qph, kph, vph, NROWS, E, E);

    gather_kernel<<<dim3(NROWS / 8, 3), 256>>>(qph, kph, vph, qidx, kidx, qg, kg, vg);

    attn_tc_kernel<<<dim3(S / 128, H, B), 128>>>(qg, kg, vg, qidx, cntq, cntk, attnh);

    tc_gemm<0, float, false><<<gE, 128, GEMM_SMEM_BYTES>>>(
        attnh, Woh, nullptr, nullptr, nullptr, nullptr, nullptr,
        att, nullptr, nullptr, NROWS, E, E);

    ln_kernel<0, __half><<<NROWS, 256>>>(att, query, ln0_g, ln0_b, mq, hh);

    tc_gemm<2, __half, false><<<gF, 128, GEMM_SMEM_BYTES>>>(
        hh, W1h, nullptr, nullptr, nullptr, nullptr, b1,
        g1h, nullptr, nullptr, NROWS, FFDIM, E);
    tc_gemm<1, float, false><<<gE, 128, GEMM_SMEM_BYTES>>>(
        g1h, W2h, nullptr, nullptr, nullptr, nullptr, b2,
        ff, nullptr, nullptr, NROWS, E, FFDIM);

    ln_kernel<1, float><<<NROWS, 256>>>(ff, query, ln1_g, ln1_b, mq, out);
}

// round 16
// speedup vs baseline: 1.2769x; 1.1333x over previous
#include <cuda_runtime.h>
#include <cuda_fp16.h>
#include <math.h>

#define E 1024
#define H 16
#define D 64
#define B 4
#define S 1024
#define NROWS (B*S)     // 4096
#define FFDIM 2048
#define ATT_SCALE 0.03125f    // 1/sqrt(1024) = 2^-5 (exact in fp16)

// ------------------------- scratch (no allocations allowed) -----------------
__device__ __half g_qh[NROWS * E];
__device__ __half g_kh[NROWS * E];
__device__ __half g_vh[NROWS * E];
__device__ __half g_Wqh[E * E];
__device__ __half g_Wkh[E * E];
__device__ __half g_Wvh[E * E];
__device__ __half g_Woh[E * E];
__device__ __half g_W1h[E * FFDIM];
__device__ __half g_W2h[FFDIM * E];
__device__ __half g_qph[NROWS * E];
__device__ __half g_kph[NROWS * E];
__device__ __half g_vph[NROWS * E];
__device__ __half g_qg[NROWS * E];      // compacted active q rows
__device__ __half g_kg[NROWS * E];      // compacted active k rows (zero padded)
__device__ __half g_vg[NROWS * E];
__device__ __half g_attnh[NROWS * E];   // attention out, COMPACT layout
__device__ float  g_att[NROWS * E];     // Wo out, COMPACT layout
__device__ __half g_hh[NROWS * E];      // LN0+res, COMPACT layout
__device__ __half g_g1h[NROWS * FFDIM]; // gelu(W1), COMPACT layout
__device__ float  g_ff[NROWS * E];      // W2 out, COMPACT layout
__device__ int    g_mq[NROWS];
__device__ int    g_mk[NROWS];
__device__ int    g_qidx[NROWS];        // per-batch compact slot -> row (-1 pad)
__device__ int    g_kidx[NROWS];
__device__ int    g_qslot[NROWS];       // row -> compact slot (-1 if masked)
__device__ int    g_cntq[B];
__device__ int    g_cntk[B];

// ------------------------- mask canonicalization -----------------------------
__device__ __forceinline__ void mask_conv_one(const void* raw, int* out, int n,
                                              int tid, int nthr, int* s_flags) {
    const unsigned char* p = (const unsigned char*)raw;
    int big = 0, nonal = 0;
    for (int i = tid; i < n; i += nthr) {
        unsigned char v = p[i];
        if (v > 1) big = 1;
        if ((i & 3) != 0 && v != 0) nonal = 1;
    }
    if (big)   atomicOr(&s_flags[0], 1);
    if (nonal) atomicOr(&s_flags[1], 1);
    __syncthreads();
    int kind = s_flags[0] ? 2 : (s_flags[1] ? 1 : 0);
    for (int i = tid; i < n; i += nthr) {
        int v;
        if (kind == 2)      v = (((const float*)raw)[i] != 0.0f);
        else if (kind == 1) v = (p[i] != 0);
        else                v = (((const int*)raw)[i] != 0);
        out[i] = v;
    }
}
__global__ void mask_convert2_kernel(const void* __restrict__ rawk, int* __restrict__ outk,
                                     const void* __restrict__ rawq, int* __restrict__ outq,
                                     int n) {
    __shared__ int fk[2], fq[2];
    if (threadIdx.x == 0) { fk[0] = fk[1] = fq[0] = fq[1] = 0; }
    __syncthreads();
    mask_conv_one(rawk, outk, n, threadIdx.x, blockDim.x, fk);
    __syncthreads();
    mask_conv_one(rawq, outq, n, threadIdx.x, blockDim.x, fq);
}

// ------------------------- index build (stable prefix scan) ------------------
__global__ __launch_bounds__(1024)
void build_index_kernel(const int* __restrict__ mq, const int* __restrict__ mk,
                        int* __restrict__ qidx, int* __restrict__ kidx,
                        int* __restrict__ qslot,
                        int* __restrict__ cntq, int* __restrict__ cntk) {
    __shared__ int sh[1024];
    const int b = blockIdx.x, t = threadIdx.x;
    // --- q ---
    int flag = mq[b * S + t];
    sh[t] = flag; __syncthreads();
    for (int off = 1; off < 1024; off <<= 1) {
        int v = (t >= off) ? sh[t - off] : 0;
        __syncthreads();
        sh[t] += v;
        __syncthreads();
    }
    int total = sh[1023];
    int excl = sh[t] - flag;
    if (flag) qidx[b * S + excl] = t;
    if (t >= total) qidx[b * S + t] = -1;
    qslot[b * S + t] = flag ? excl : -1;
    if (t == 0) cntq[b] = total;
    __syncthreads();
    // --- k ---
    flag = mk[b * S + t];
    sh[t] = flag; __syncthreads();
    for (int off = 1; off < 1024; off <<= 1) {
        int v = (t >= off) ? sh[t - off] : 0;
        __syncthreads();
        sh[t] += v;
        __syncthreads();
    }
    total = sh[1023];
    excl = sh[t] - flag;
    if (flag) kidx[b * S + excl] = t;
    if (t >= total) kidx[b * S + t] = -1;
    if (t == 0) cntk[b] = total;
}

// ------------------------- gather active rows --------------------------------
// blockIdx.y: 0=q(qidx), 1=k(kidx), 2=v(kidx). One warp per compact row.
__global__ __launch_bounds__(256)
void gather_kernel(const __half* __restrict__ qp, const __half* __restrict__ kp,
                   const __half* __restrict__ vp,
                   const int* __restrict__ qidx, const int* __restrict__ kidx,
                   __half* __restrict__ qg, __half* __restrict__ kg,
                   __half* __restrict__ vg) {
    const int warp = threadIdx.x >> 5, lane = threadIdx.x & 31;
    const int r = blockIdx.x * 8 + warp;
    const int b = r >> 10;
    const __half* src;  __half* dst;  int row;
    if (blockIdx.y == 0) { row = qidx[r]; src = qp; dst = qg; }
    else if (blockIdx.y == 1) { row = kidx[r]; src = kp; dst = kg; }
    else { row = kidx[r]; src = vp; dst = vg; }
    uint4* d = (uint4*)(dst + (size_t)r * E);
    if (row >= 0) {
        const uint4* s = (const uint4*)(src + (size_t)(b * S + row) * E);
        d[lane] = s[lane];
        d[lane + 32] = s[lane + 32];
        d[lane + 64] = s[lane + 64];
        d[lane + 96] = s[lane + 96];
    } else {
        uint4 z = {0, 0, 0, 0};
        d[lane] = z;
        d[lane + 32] = z;
        d[lane + 64] = z;
        d[lane + 96] = z;
    }
}

// ------------------------- fused fp32 -> fp16 conversion ---------------------
#define Q_NE (NROWS * E / 4)
#define Q_EE (E * E / 4)
#define Q_EF (E * FFDIM / 4)

__global__ __launch_bounds__(256)
void f2h_all_kernel(const float* s0, __half* d0, const float* s1, __half* d1,
                    const float* s2, __half* d2, const float* s3, __half* d3,
                    const float* s4, __half* d4, const float* s5, __half* d5,
                    const float* s6, __half* d6, const float* s7, __half* d7,
                    const float* s8, __half* d8) {
    const float* src; __half* dst; int n4;
    switch (blockIdx.y) {
        case 0: src = s0; dst = d0; n4 = Q_NE; break;
        case 1: src = s1; dst = d1; n4 = Q_NE; break;
        case 2: src = s2; dst = d2; n4 = Q_NE; break;
        case 3: src = s3; dst = d3; n4 = Q_EE; break;
        case 4: src = s4; dst = d4; n4 = Q_EE; break;
        case 5: src = s5; dst = d5; n4 = Q_EE; break;
        case 6: src = s6; dst = d6; n4 = Q_EE; break;
        case 7: src = s7; dst = d7; n4 = Q_EF; break;
        default: src = s8; dst = d8; n4 = Q_EF; break;
    }
    int i = blockIdx.x * blockDim.x + threadIdx.x;
    const int stride = gridDim.x * blockDim.x;
    for (; i < n4; i += stride) {
        float4 v = ((const float4*)src)[i];
        __half2* o = (__half2*)dst + 2 * i;
        o[0] = __floats2half2_rn(v.x, v.y);
        o[1] = __floats2half2_rn(v.z, v.w);
    }
}

// ------------------------- mma / ldmatrix helpers ----------------------------
__device__ __forceinline__ unsigned h2u(__half2 h) {
    union { __half2 h; unsigned u; } c; c.h = h; return c.u;
}
__device__ __forceinline__ unsigned u2hm(unsigned u, __half2 s) {
    union { __half2 h; unsigned u; } c; c.u = u;
    c.h = __hmul2(c.h, s);
    return c.u;
}
__device__ __forceinline__ void mma16(float c[4], const unsigned a[4], const unsigned b[2]) {
    asm volatile(
        "mma.sync.aligned.m16n8k16.row.col.f32.f16.f16.f32 "
        "{%0,%1,%2,%3}, {%4,%5,%6,%7}, {%8,%9}, {%0,%1,%2,%3};"
        : "+f"(c[0]), "+f"(c[1]), "+f"(c[2]), "+f"(c[3])
        : "r"(a[0]), "r"(a[1]), "r"(a[2]), "r"(a[3]), "r"(b[0]), "r"(b[1]));
}
__device__ __forceinline__ void ldsm4(unsigned r[4], unsigned saddr) {
    asm volatile("ldmatrix.sync.aligned.m8n8.x4.shared.b16 {%0,%1,%2,%3}, [%4];"
                 : "=r"(r[0]), "=r"(r[1]), "=r"(r[2]), "=r"(r[3]) : "r"(saddr));
}
__device__ __forceinline__ void ldsm4t(unsigned r[4], unsigned saddr) {
    asm volatile("ldmatrix.sync.aligned.m8n8.x4.trans.shared.b16 {%0,%1,%2,%3}, [%4];"
                 : "=r"(r[0]), "=r"(r[1]), "=r"(r[2]), "=r"(r[3]) : "r"(saddr));
}
__device__ __forceinline__ void cp16(void* smem, const void* g) {
    unsigned s = (unsigned)__cvta_generic_to_shared(smem);
    asm volatile("cp.async.cg.shared.global [%0], [%1], 16;\n" :: "r"(s), "l"(g));
}
__device__ __forceinline__ void cp_commit() { asm volatile("cp.async.commit_group;\n"); }
template<int N> __device__ __forceinline__ void cp_wait() {
    asm volatile("cp.async.wait_group %0;\n" :: "n"(N));
}

// ------------------------- fp16 tensor-core GEMM -----------------------------
// COMPACT: per-batch compact row layout; block exits if its 128-row window is
// entirely past cntq[batch]. Padding rows compute garbage (never read).
#define ASTR 40
#define BSTR 136
#define GSTAGES 4
#define STAGE_H (128 * ASTR + 32 * BSTR)
#define GEMM_SMEM_BYTES (GSTAGES * STAGE_H * 2)

template<int EPI, typename OutT, bool QKV3, bool COMPACT>
__global__ __launch_bounds__(128, 2)
void tc_gemm(const __half* __restrict__ A0, const __half* __restrict__ B0,
             const __half* __restrict__ A1, const __half* __restrict__ B1,
             const __half* __restrict__ A2, const __half* __restrict__ B2,
             const float* __restrict__ bias, OutT* __restrict__ C0,
             OutT* __restrict__ C1, OutT* __restrict__ C2,
             const int* __restrict__ cntp,
             int M, int N, int K) {
    extern __shared__ __half smem[];
    const int bm = blockIdx.y * 128, bn = blockIdx.x * 128;
    if (COMPACT) {
        const int batch = bm >> 10;
        if ((bm & (S - 1)) >= cntp[batch]) return;   // uniform exit
    }
    const __half* A = A0; const __half* Bm = B0; OutT* C = C0;
    if (QKV3) {
        if (blockIdx.z == 1) { A = A1; Bm = B1; C = C1; }
        else if (blockIdx.z == 2) { A = A2; Bm = B2; C = C2; }
    }
    const int tid = threadIdx.x;
    const int warp = tid >> 5, lane = tid & 31;
    const int wm = (warp & 1) * 64;
    const int wn = (warp >> 1) * 64;
    const int g = lane >> 2, t4 = lane & 3;
    const int l16 = lane & 15, lhi = (lane & 16) ? 8 : 0;

    const unsigned sbase = (unsigned)__cvta_generic_to_shared(smem);

    float c[4][8][4];
#pragma unroll
    for (int i = 0; i < 4; i++)
#pragma unroll
        for (int j = 0; j < 8; j++)
#pragma unroll
            for (int r = 0; r < 4; r++) c[i][j][r] = 0.0f;

    auto load_stage = [&](int buf, int tI) {
        __half* As = smem + buf * STAGE_H;
        __half* Bs = As + 128 * ASTR;
#pragma unroll
        for (int q = 0; q < 4; q++) {
            int ch = tid + 128 * q;
            int ar = ch >> 2, acc_ = (ch & 3) * 8;
            cp16(&As[ar * ASTR + acc_], A + (size_t)(bm + ar) * K + tI * 32 + acc_);
            int brr = ch >> 4, bcc = (ch & 15) * 8;
            cp16(&Bs[brr * BSTR + bcc], Bm + (size_t)(tI * 32 + brr) * N + bn + bcc);
        }
    };

    const int T = K / 32;
#pragma unroll
    for (int s = 0; s < GSTAGES - 1; s++) {
        load_stage(s, s);
        cp_commit();
    }

    for (int tI = 0; tI < T; tI++) {
        const int buf = tI & (GSTAGES - 1);
        cp_wait<GSTAGES - 2>();
        __syncthreads();
        if (tI + GSTAGES - 1 < T)
            load_stage((tI + GSTAGES - 1) & (GSTAGES - 1), tI + GSTAGES - 1);
        cp_commit();

        const unsigned sA = sbase + 2u * (buf * STAGE_H);
        const unsigned sB = sA + 2u * (128 * ASTR);
#pragma unroll
        for (int step = 0; step < 2; step++) {
            const int k0 = step * 16;
            unsigned af[4][4], bf[8][2];
#pragma unroll
            for (int i = 0; i < 4; i++) {
                unsigned addr = sA + 2u * ((wm + i * 16 + l16) * ASTR + k0 + lhi);
                ldsm4(af[i], addr);
            }
#pragma unroll
            for (int jp = 0; jp < 4; jp++) {
                unsigned addr = sB + 2u * ((k0 + l16) * BSTR + wn + jp * 16 + lhi);
                unsigned r[4];
                ldsm4t(r, addr);
                bf[2 * jp][0] = r[0];     bf[2 * jp][1] = r[1];
                bf[2 * jp + 1][0] = r[2]; bf[2 * jp + 1][1] = r[3];
            }
#pragma unroll
            for (int i = 0; i < 4; i++)
#pragma unroll
                for (int j = 0; j < 8; j++)
                    mma16(c[i][j], af[i], bf[j]);
        }
    }

#pragma unroll
    for (int i = 0; i < 4; i++) {
#pragma unroll
        for (int j = 0; j < 8; j++) {
            const int row0 = bm + wm + i * 16 + g;
            const int col = bn + wn + j * 8 + 2 * t4;
            float v0 = c[i][j][0], v1 = c[i][j][1], v2 = c[i][j][2], v3 = c[i][j][3];
            if (EPI >= 1) {
                float b0 = bias[col], b1 = bias[col + 1];
                v0 += b0; v1 += b1; v2 += b0; v3 += b1;
            }
            if (EPI == 2) {
                v0 *= 1.0f / (1.0f + __expf(-1.702f * v0));
                v1 *= 1.0f / (1.0f + __expf(-1.702f * v1));
                v2 *= 1.0f / (1.0f + __expf(-1.702f * v2));
                v3 *= 1.0f / (1.0f + __expf(-1.702f * v3));
            }
            if (sizeof(OutT) == 2) {
                *(__half2*)((__half*)C + (size_t)row0 * N + col) = __floats2half2_rn(v0, v1);
                *(__half2*)((__half*)C + (size_t)(row0 + 8) * N + col) = __floats2half2_rn(v2, v3);
            } else {
                float2 p0 = {v0, v1}, p1 = {v2, v3};
                *(float2*)((float*)C + (size_t)row0 * N + col) = p0;
                *(float2*)((float*)C + (size_t)(row0 + 8) * N + col) = p1;
            }
        }
    }
}

// ------------------------- compacted fp16 flash attention --------------------
// Output written in COMPACT layout (no scatter).
#define KVSTR 72
#define KB 32

__global__ __launch_bounds__(128, 3)
void attn_tc_kernel(const __half* __restrict__ qg, const __half* __restrict__ kg,
                    const __half* __restrict__ vg,
                    const int* __restrict__ cntq_a, const int* __restrict__ cntk_a,
                    __half* __restrict__ out) {
    __shared__ __half Ks[2][KB * KVSTR];
    __shared__ __half Vs[2][KB * KVSTR];

    const int b = blockIdx.z, h = blockIdx.y;
    const int q0 = blockIdx.x * 128;
    const int cntq = cntq_a[b];
    if (q0 >= cntq) return;
    const int cntk = cntk_a[b];
    const int nkt = (cntk + KB - 1) / KB;

    const int tid = threadIdx.x;
    const int w = tid >> 5, lane = tid & 31;
    const int g = lane >> 2, t4 = lane & 3;
    const int l16 = lane & 15, lhi = (lane & 16) ? 8 : 0;
    const int l8 = lane & 7, lm = ((lane & 8) ? 8 : 0), ln16 = (lane & 16) ? 8 : 0;

    const unsigned sK0 = (unsigned)__cvta_generic_to_shared(&Ks[0][0]);
    const unsigned sK1 = (unsigned)__cvta_generic_to_shared(&Ks[1][0]);
    const unsigned sV0 = (unsigned)__cvta_generic_to_shared(&Vs[0][0]);
    const unsigned sV1 = (unsigned)__cvta_generic_to_shared(&Vs[1][0]);

    const __half2 qscale = __float2half2_rn(ATT_SCALE);
    unsigned qa[2][4][4];
#pragma unroll
    for (int i = 0; i < 2; i++) {
        const __half* Qr0 = qg + (size_t)(b * S + q0 + w * 32 + i * 16 + g) * E + h * D;
        const __half* Qr1 = Qr0 + (size_t)8 * E;
#pragma unroll
        for (int s = 0; s < 4; s++) {
            qa[i][s][0] = u2hm(*(const unsigned*)&Qr0[16 * s + 2 * t4], qscale);
            qa[i][s][1] = u2hm(*(const unsigned*)&Qr1[16 * s + 2 * t4], qscale);
            qa[i][s][2] = u2hm(*(const unsigned*)&Qr0[16 * s + 8 + 2 * t4], qscale);
            qa[i][s][3] = u2hm(*(const unsigned*)&Qr1[16 * s + 8 + 2 * t4], qscale);
        }
    }

    float oacc[2][8][4];
#pragma unroll
    for (int i = 0; i < 2; i++)
#pragma unroll
        for (int n = 0; n < 8; n++)
#pragma unroll
            for (int r = 0; r < 4; r++) oacc[i][n][r] = 0.0f;
    float lsum[2][2] = {{0.0f, 0.0f}, {0.0f, 0.0f}};

    auto load_tiles = [&](int kt, int buf) {
        int key = tid >> 2, c8 = (tid & 3) * 16;
        const __half* gk = kg + (size_t)(b * S + kt + key) * E + h * D + c8;
        const __half* gv = vg + (size_t)(b * S + kt + key) * E + h * D + c8;
        cp16(&Ks[buf][key * KVSTR + c8], gk);
        cp16(&Ks[buf][key * KVSTR + c8 + 8], gk + 8);
        cp16(&Vs[buf][key * KVSTR + c8], gv);
        cp16(&Vs[buf][key * KVSTR + c8 + 8], gv + 8);
    };

    load_tiles(0, 0);
    cp_commit();

    for (int kb = 0; kb < nkt; kb++) {
        const int buf = kb & 1;
        if (kb + 1 < nkt) {
            load_tiles((kb + 1) * KB, buf ^ 1);
            cp_commit();
            cp_wait<1>();
        } else {
            cp_wait<0>();
        }
        __syncthreads();

        const unsigned sK = buf ? sK1 : sK0;
        const unsigned sV = buf ? sV1 : sV0;

        float sc[2][4][4];
#pragma unroll
        for (int i = 0; i < 2; i++)
#pragma unroll
            for (int j = 0; j < 4; j++)
#pragma unroll
                for (int r = 0; r < 4; r++) sc[i][j][r] = 0.0f;
#pragma unroll
        for (int s = 0; s < 4; s++) {
#pragma unroll
            for (int jp = 0; jp < 2; jp++) {
                unsigned addr = sK + 2u * ((jp * 16 + l8 + ln16) * KVSTR + 16 * s + lm);
                unsigned r[4];
                ldsm4(r, addr);
                unsigned bf0[2] = {r[0], r[1]};
                unsigned bf1[2] = {r[2], r[3]};
#pragma unroll
                for (int i = 0; i < 2; i++) {
                    mma16(sc[i][2 * jp], qa[i][s], bf0);
                    mma16(sc[i][2 * jp + 1], qa[i][s], bf1);
                }
            }
        }

        const int kbase = kb * KB;
        unsigned pp[2][4][2];
#pragma unroll
        for (int i = 0; i < 2; i++) {
#pragma unroll
            for (int j = 0; j < 4; j++) {
                const int c0 = 8 * j + 2 * t4;
                float m0 = (kbase + c0 < cntk) ? 1.0f : 0.0f;
                float m1 = (kbase + c0 + 1 < cntk) ? 1.0f : 0.0f;
                float p0 = __expf(sc[i][j][0]) * m0;
                float p1 = __expf(sc[i][j][1]) * m1;
                float p2 = __expf(sc[i][j][2]) * m0;
                float p3 = __expf(sc[i][j][3]) * m1;
                lsum[i][0] += p0 + p1;
                lsum[i][1] += p2 + p3;
                pp[i][j][0] = h2u(__floats2half2_rn(p0, p1));
                pp[i][j][1] = h2u(__floats2half2_rn(p2, p3));
            }
        }

#pragma unroll
        for (int s = 0; s < 2; s++) {
            unsigned pa[2][4];
#pragma unroll
            for (int i = 0; i < 2; i++) {
                pa[i][0] = pp[i][2 * s][0]; pa[i][1] = pp[i][2 * s][1];
                pa[i][2] = pp[i][2 * s + 1][0]; pa[i][3] = pp[i][2 * s + 1][1];
            }
#pragma unroll
            for (int np = 0; np < 4; np++) {
                unsigned addr = sV + 2u * ((16 * s + l16) * KVSTR + np * 16 + lhi);
                unsigned r[4];
                ldsm4t(r, addr);
                unsigned bf0[2] = {r[0], r[1]};
                unsigned bf1[2] = {r[2], r[3]};
#pragma unroll
                for (int i = 0; i < 2; i++) {
                    mma16(oacc[i][2 * np], pa[i], bf0);
                    mma16(oacc[i][2 * np + 1], pa[i], bf1);
                }
            }
        }
        __syncthreads();
    }

#pragma unroll
    for (int i = 0; i < 2; i++) {
        float l0 = lsum[i][0], l1 = lsum[i][1];
        l0 += __shfl_xor_sync(0xffffffffu, l0, 1);
        l0 += __shfl_xor_sync(0xffffffffu, l0, 2);
        l1 += __shfl_xor_sync(0xffffffffu, l1, 1);
        l1 += __shfl_xor_sync(0xffffffffu, l1, 2);

        const int slot0 = b * S + q0 + w * 32 + i * 16 + g;
        const float inv0 = 1.0f / l0;
        const float inv1 = 1.0f / l1;
        __half* o0 = out + (size_t)slot0 * E + h * D;
        __half* o1 = o0 + (size_t)8 * E;
#pragma unroll
        for (int n = 0; n < 8; n++) {
            const int c0 = 8 * n + 2 * t4;
            *(__half2*)(o0 + c0) = __floats2half2_rn(oacc[i][n][0] * inv0, oacc[i][n][1] * inv0);
            *(__half2*)(o1 + c0) = __floats2half2_rn(oacc[i][n][2] * inv1, oacc[i][n][3] * inv1);
        }
    }
}

// ------------------------- layernorm variants --------------------------------
// MODE 0 (compact): block=slot r; orig=qidx[r]; if orig<0 write 0s to hh[r];
//   else hh[r] = LN(att[r]) + query[orig]   (active rows have mask=1)
// MODE 1 (final):   block=orig row; if !mask write 0s to out[row];
//   else r=qslot[row]; out[row] = LN(ff[r] + query[row])
template<int MODE, typename OutT>
__global__ __launch_bounds__(256)
void ln_kernel(const float* __restrict__ x, const float* __restrict__ res,
               const float* __restrict__ g, const float* __restrict__ bb,
               const int* __restrict__ idx_or_mask, const int* __restrict__ qslot,
               OutT* __restrict__ out) {
    __shared__ float s1[256], s2[256];
    const int blk = blockIdx.x;
    const int tid = threadIdx.x;

    int xrow, resrow, orow;
    bool active;
    if (MODE == 0) {
        int orig = idx_or_mask[blk];     // qidx
        active = (orig >= 0);
        xrow = blk; resrow = (blk & ~(S - 1)) + (active ? orig : 0); orow = blk;
    } else {
        active = (idx_or_mask[blk] != 0);   // mq
        int r = active ? qslot[blk] : 0;
        xrow = (blk & ~(S - 1)) + r; resrow = blk; orow = blk;
    }

    if (!active) {
        for (int i = 0; i < 4; i++) {
            int c = tid + i * 256;
            if (sizeof(OutT) == 2) ((__half*)out)[(size_t)orow * E + c] = __float2half(0.0f);
            else                   ((float*)out)[(size_t)orow * E + c] = 0.0f;
        }
        return;
    }

    const float* xr = x + (size_t)xrow * E;
    const float* rr = res + (size_t)resrow * E;
    float v[4];
    float s = 0.0f, sq = 0.0f;
#pragma unroll
    for (int i = 0; i < 4; i++) {
        int c = tid + i * 256;
        float t = xr[c];
        if (MODE == 1) t += rr[c];
        v[i] = t; s += t; sq += t * t;
    }
    s1[tid] = s; s2[tid] = sq;
    __syncthreads();
    for (int off = 128; off > 0; off >>= 1) {
        if (tid < off) { s1[tid] += s1[tid + off]; s2[tid] += s2[tid + off]; }
        __syncthreads();
    }
    float mu = s1[0] * (1.0f / E);
    float var = s2[0] * (1.0f / E) - mu * mu;
    float rstd = rsqrtf(var + 1e-5f);
#pragma unroll
    for (int i = 0; i < 4; i++) {
        int c = tid + i * 256;
        float y = (v[i] - mu) * rstd * g[c] + bb[c];
        float o = (MODE == 0) ? (y + rr[c]) : y;
        if (sizeof(OutT) == 2) ((__half*)out)[(size_t)orow * E + c] = __float2half(o);
        else                   ((float*)out)[(size_t)orow * E + c] = o;
    }
}

// ------------------------- launch -------------------------------------------
extern "C" void kernel_launch(void* const* d_in, const int* in_sizes, int n_in,
                              void* d_out, int out_size) {
    const float* value = (const float*)d_in[0];
    const float* key   = (const float*)d_in[1];
    const float* query = (const float*)d_in[2];
    const void*  mask_k_raw = d_in[3];
    const void*  mask_q_raw = d_in[4];
    const float* Wv = (const float*)d_in[5];
    const float* Wk = (const float*)d_in[6];
    const float* Wq = (const float*)d_in[7];
    const float* Wo = (const float*)d_in[8];
    const float* ln0_g = (const float*)d_in[9];
    const float* ln0_b = (const float*)d_in[10];
    const float* W1 = (const float*)d_in[11];
    const float* b1 = (const float*)d_in[12];
    const float* W2 = (const float*)d_in[13];
    const float* b2 = (const float*)d_in[14];
    const float* ln1_g = (const float*)d_in[15];
    const float* ln1_b = (const float*)d_in[16];
    float* out = (float*)d_out;

    __half *qh, *kh, *vh, *Wqh, *Wkh, *Wvh, *Woh, *W1h, *W2h;
    __half *qph, *kph, *vph, *qg, *kg, *vg, *attnh, *hh, *g1h;
    float *att, *ff;
    int *mq, *mk, *qidx, *kidx, *qslot, *cntq, *cntk;
    cudaGetSymbolAddress((void**)&qh,   g_qh);
    cudaGetSymbolAddress((void**)&kh,   g_kh);
    cudaGetSymbolAddress((void**)&vh,   g_vh);
    cudaGetSymbolAddress((void**)&Wqh,  g_Wqh);
    cudaGetSymbolAddress((void**)&Wkh,  g_Wkh);
    cudaGetSymbolAddress((void**)&Wvh,  g_Wvh);
    cudaGetSymbolAddress((void**)&Woh,  g_Woh);
    cudaGetSymbolAddress((void**)&W1h,  g_W1h);
    cudaGetSymbolAddress((void**)&W2h,  g_W2h);
    cudaGetSymbolAddress((void**)&qph,  g_qph);
    cudaGetSymbolAddress((void**)&kph,  g_kph);
    cudaGetSymbolAddress((void**)&vph,  g_vph);
    cudaGetSymbolAddress((void**)&qg,   g_qg);
    cudaGetSymbolAddress((void**)&kg,   g_kg);
    cudaGetSymbolAddress((void**)&vg,   g_vg);
    cudaGetSymbolAddress((void**)&attnh,g_attnh);
    cudaGetSymbolAddress((void**)&hh,   g_hh);
    cudaGetSymbolAddress((void**)&g1h,  g_g1h);
    cudaGetSymbolAddress((void**)&att,  g_att);
    cudaGetSymbolAddress((void**)&ff,   g_ff);
    cudaGetSymbolAddress((void**)&mq,   g_mq);
    cudaGetSymbolAddress((void**)&mk,   g_mk);
    cudaGetSymbolAddress((void**)&qidx, g_qidx);
    cudaGetSymbolAddress((void**)&kidx, g_kidx);
    cudaGetSymbolAddress((void**)&qslot,g_qslot);
    cudaGetSymbolAddress((void**)&cntq, g_cntq);
    cudaGetSymbolAddress((void**)&cntk, g_cntk);

    cudaFuncSetAttribute(tc_gemm<0, __half, true, false>, cudaFuncAttributeMaxDynamicSharedMemorySize, GEMM_SMEM_BYTES);
    cudaFuncSetAttribute(tc_gemm<0, float, false, true>,  cudaFuncAttributeMaxDynamicSharedMemorySize, GEMM_SMEM_BYTES);
    cudaFuncSetAttribute(tc_gemm<1, float, false, true>,  cudaFuncAttributeMaxDynamicSharedMemorySize, GEMM_SMEM_BYTES);
    cudaFuncSetAttribute(tc_gemm<2, __half, false, true>, cudaFuncAttributeMaxDynamicSharedMemorySize, GEMM_SMEM_BYTES);

    mask_convert2_kernel<<<1, 256>>>(mask_k_raw, mk, mask_q_raw, mq, NROWS);
    build_index_kernel<<<B, 1024>>>(mq, mk, qidx, kidx, qslot, cntq, cntk);

    f2h_all_kernel<<<dim3(160, 9), 256>>>(query, qh, key, kh, value, vh,
                                          Wq, Wqh, Wk, Wkh, Wv, Wvh, Wo, Woh,
                                          W1, W1h, W2, W2h);

    dim3 gE3(E / 128, NROWS / 128, 3);
    dim3 gE(E / 128, NROWS / 128);
    dim3 gF(FFDIM / 128, NROWS / 128);

    tc_gemm<0, __half, true, false><<<gE3, 128, GEMM_SMEM_BYTES>>>(
        qh, Wqh, kh, Wkh, vh, Wvh, nullptr, qph, kph, vph, nullptr, NROWS, E, E);

    gather_kernel<<<dim3(NROWS / 8, 3), 256>>>(qph, kph, vph, qidx, kidx, qg, kg, vg);

    attn_tc_kernel<<<dim3(S / 128, H, B), 128>>>(qg, kg, vg, cntq, cntk, attnh);

    // Wo GEMM on compact rows
    tc_gemm<0, float, false, true><<<gE, 128, GEMM_SMEM_BYTES>>>(
        attnh, Woh, nullptr, nullptr, nullptr, nullptr, nullptr,
        att, nullptr, nullptr, cntq, NROWS, E, E);

    // h[r] = LN0(att[r]) + query[qidx[r]]  (compact layout)
    ln_kernel<0, __half><<<NROWS, 256>>>(att, query, ln0_g, ln0_b, qidx, qslot, hh);

    tc_gemm<2, __half, false, true><<<gF, 128, GEMM_SMEM_BYTES>>>(
        hh, W1h, nullptr, nullptr, nullptr, nullptr, b1,
        g1h, nullptr, nullptr, cntq, NROWS, FFDIM, E);
    tc_gemm<1, float, false, true><<<gE, 128, GEMM_SMEM_BYTES>>>(
        g1h, W2h, nullptr, nullptr, nullptr, nullptr, b2,
        ff, nullptr, nullptr, cntq, NROWS, E, FFDIM);

    // out[row] = mask ? LN1(ff[qslot[row]] + query[row]) : 0
    ln_kernel<1, float><<<NROWS, 256>>>(ff, query, ln1_g, ln1_b, mq, qslot, out);
}

// round 17
// speedup vs baseline: 1.4416x; 1.1290x over previous
#include <cuda_runtime.h>
#include <cuda_fp16.h>
#include <math.h>

#define E 1024
#define H 16
#define D 64
#define B 4
#define S 1024
#define NROWS (B*S)     // 4096
#define FFDIM 2048
#define ATT_SCALE 0.03125f    // 1/sqrt(1024) = 2^-5 (exact in fp16)

// ------------------------- scratch (no allocations allowed) -----------------
__device__ __half g_qin[NROWS * E];     // compact fp16 query input
__device__ __half g_kin[NROWS * E];     // compact fp16 key input
__device__ __half g_vin[NROWS * E];     // compact fp16 value input
__device__ __half g_Wqh[E * E];
__device__ __half g_Wkh[E * E];
__device__ __half g_Wvh[E * E];
__device__ __half g_Woh[E * E];
__device__ __half g_W1h[E * FFDIM];
__device__ __half g_W2h[FFDIM * E];
__device__ __half g_qg[NROWS * E];      // compact q projections
__device__ __half g_kg[NROWS * E];      // compact k projections
__device__ __half g_vg[NROWS * E];      // compact v projections
__device__ __half g_attnh[NROWS * E];   // attention out, COMPACT layout
__device__ float  g_att[NROWS * E];     // Wo out, COMPACT layout
__device__ __half g_hh[NROWS * E];      // LN0+res, COMPACT layout
__device__ __half g_g1h[NROWS * FFDIM]; // gelu(W1), COMPACT layout
__device__ float  g_ff[NROWS * E];      // W2 out, COMPACT layout
__device__ int    g_mq[NROWS];
__device__ int    g_mk[NROWS];
__device__ int    g_qidx[NROWS];        // per-batch compact slot -> row (-1 pad)
__device__ int    g_kidx[NROWS];
__device__ int    g_qslot[NROWS];       // row -> compact slot (-1 if masked)
__device__ int    g_cntq[B];
__device__ int    g_cntk[B];

// ------------------------- mask canonicalization -----------------------------
__device__ __forceinline__ void mask_conv_one(const void* raw, int* out, int n,
                                              int tid, int nthr, int* s_flags) {
    const unsigned char* p = (const unsigned char*)raw;
    int big = 0, nonal = 0;
    for (int i = tid; i < n; i += nthr) {
        unsigned char v = p[i];
        if (v > 1) big = 1;
        if ((i & 3) != 0 && v != 0) nonal = 1;
    }
    if (big)   atomicOr(&s_flags[0], 1);
    if (nonal) atomicOr(&s_flags[1], 1);
    __syncthreads();
    int kind = s_flags[0] ? 2 : (s_flags[1] ? 1 : 0);
    for (int i = tid; i < n; i += nthr) {
        int v;
        if (kind == 2)      v = (((const float*)raw)[i] != 0.0f);
        else if (kind == 1) v = (p[i] != 0);
        else                v = (((const int*)raw)[i] != 0);
        out[i] = v;
    }
}
__global__ void mask_convert2_kernel(const void* __restrict__ rawk, int* __restrict__ outk,
                                     const void* __restrict__ rawq, int* __restrict__ outq,
                                     int n) {
    __shared__ int fk[2], fq[2];
    if (threadIdx.x == 0) { fk[0] = fk[1] = fq[0] = fq[1] = 0; }
    __syncthreads();
    mask_conv_one(rawk, outk, n, threadIdx.x, blockDim.x, fk);
    __syncthreads();
    mask_conv_one(rawq, outq, n, threadIdx.x, blockDim.x, fq);
}

// ------------------------- index build (stable prefix scan) ------------------
__global__ __launch_bounds__(1024)
void build_index_kernel(const int* __restrict__ mq, const int* __restrict__ mk,
                        int* __restrict__ qidx, int* __restrict__ kidx,
                        int* __restrict__ qslot,
                        int* __restrict__ cntq, int* __restrict__ cntk) {
    __shared__ int sh[1024];
    const int b = blockIdx.x, t = threadIdx.x;
    int flag = mq[b * S + t];
    sh[t] = flag; __syncthreads();
    for (int off = 1; off < 1024; off <<= 1) {
        int v = (t >= off) ? sh[t - off] : 0;
        __syncthreads();
        sh[t] += v;
        __syncthreads();
    }
    int total = sh[1023];
    int excl = sh[t] - flag;
    if (flag) qidx[b * S + excl] = t;
    if (t >= total) qidx[b * S + t] = -1;
    qslot[b * S + t] = flag ? excl : -1;
    if (t == 0) cntq[b] = total;
    __syncthreads();
    flag = mk[b * S + t];
    sh[t] = flag; __syncthreads();
    for (int off = 1; off < 1024; off <<= 1) {
        int v = (t >= off) ? sh[t - off] : 0;
        __syncthreads();
        sh[t] += v;
        __syncthreads();
    }
    total = sh[1023];
    excl = sh[t] - flag;
    if (flag) kidx[b * S + excl] = t;
    if (t >= total) kidx[b * S + t] = -1;
    if (t == 0) cntk[b] = total;
}

// ------------------------- fused gather + fp32->fp16 (activations) -----------
// blockIdx.y: 0=query(qidx), 1=key(kidx), 2=value(kidx). One warp per compact
// row: 1024 floats = 256 float4 -> 8 float4/lane; write 8 x 16B fp16 chunks.
__global__ __launch_bounds__(256)
void gav_kernel(const float* __restrict__ q, const float* __restrict__ k,
                const float* __restrict__ v,
                const int* __restrict__ qidx, const int* __restrict__ kidx,
                __half* __restrict__ qo, __half* __restrict__ ko,
                __half* __restrict__ vo) {
    const int warp = threadIdx.x >> 5, lane = threadIdx.x & 31;
    const int r = blockIdx.x * 8 + warp;
    const int b = r >> 10;
    const float* src; __half* dst; int row;
    if (blockIdx.y == 0) { row = qidx[r]; src = q; dst = qo; }
    else if (blockIdx.y == 1) { row = kidx[r]; src = k; dst = ko; }
    else { row = kidx[r]; src = v; dst = vo; }
    __half2* d = (__half2*)(dst + (size_t)r * E);
    if (row >= 0) {
        const float4* s = (const float4*)(src + (size_t)(b * S + row) * E);
#pragma unroll
        for (int i = 0; i < 8; i++) {
            float4 x = s[lane + 32 * i];
            d[2 * (lane + 32 * i)]     = __floats2half2_rn(x.x, x.y);
            d[2 * (lane + 32 * i) + 1] = __floats2half2_rn(x.z, x.w);
        }
    } else {
        __half2 z = __floats2half2_rn(0.0f, 0.0f);
#pragma unroll
        for (int i = 0; i < 8; i++) {
            d[2 * (lane + 32 * i)] = z;
            d[2 * (lane + 32 * i) + 1] = z;
        }
    }
}

// ------------------------- fp32 -> fp16 conversion (weights only) ------------
#define Q_EE (E * E / 4)
#define Q_EF (E * FFDIM / 4)

__global__ __launch_bounds__(256)
void f2h_w_kernel(const float* s0, __half* d0, const float* s1, __half* d1,
                  const float* s2, __half* d2, const float* s3, __half* d3,
                  const float* s4, __half* d4, const float* s5, __half* d5) {
    const float* src; __half* dst; int n4;
    switch (blockIdx.y) {
        case 0: src = s0; dst = d0; n4 = Q_EE; break;
        case 1: src = s1; dst = d1; n4 = Q_EE; break;
        case 2: src = s2; dst = d2; n4 = Q_EE; break;
        case 3: src = s3; dst = d3; n4 = Q_EE; break;
        case 4: src = s4; dst = d4; n4 = Q_EF; break;
        default: src = s5; dst = d5; n4 = Q_EF; break;
    }
    int i = blockIdx.x * blockDim.x + threadIdx.x;
    const int stride = gridDim.x * blockDim.x;
    for (; i < n4; i += stride) {
        float4 v = ((const float4*)src)[i];
        __half2* o = (__half2*)dst + 2 * i;
        o[0] = __floats2half2_rn(v.x, v.y);
        o[1] = __floats2half2_rn(v.z, v.w);
    }
}

// ------------------------- mma / ldmatrix helpers ----------------------------
__device__ __forceinline__ unsigned h2u(__half2 h) {
    union { __half2 h; unsigned u; } c; c.h = h; return c.u;
}
__device__ __forceinline__ unsigned u2hm(unsigned u, __half2 s) {
    union { __half2 h; unsigned u; } c; c.u = u;
    c.h = __hmul2(c.h, s);
    return c.u;
}
__device__ __forceinline__ void mma16(float c[4], const unsigned a[4], const unsigned b[2]) {
    asm volatile(
        "mma.sync.aligned.m16n8k16.row.col.f32.f16.f16.f32 "
        "{%0,%1,%2,%3}, {%4,%5,%6,%7}, {%8,%9}, {%0,%1,%2,%3};"
        : "+f"(c[0]), "+f"(c[1]), "+f"(c[2]), "+f"(c[3])
        : "r"(a[0]), "r"(a[1]), "r"(a[2]), "r"(a[3]), "r"(b[0]), "r"(b[1]));
}
__device__ __forceinline__ void ldsm4(unsigned r[4], unsigned saddr) {
    asm volatile("ldmatrix.sync.aligned.m8n8.x4.shared.b16 {%0,%1,%2,%3}, [%4];"
                 : "=r"(r[0]), "=r"(r[1]), "=r"(r[2]), "=r"(r[3]) : "r"(saddr));
}
__device__ __forceinline__ void ldsm4t(unsigned r[4], unsigned saddr) {
    asm volatile("ldmatrix.sync.aligned.m8n8.x4.trans.shared.b16 {%0,%1,%2,%3}, [%4];"
                 : "=r"(r[0]), "=r"(r[1]), "=r"(r[2]), "=r"(r[3]) : "r"(saddr));
}
__device__ __forceinline__ void cp16(void* smem, const void* g) {
    unsigned s = (unsigned)__cvta_generic_to_shared(smem);
    asm volatile("cp.async.cg.shared.global [%0], [%1], 16;\n" :: "r"(s), "l"(g));
}
__device__ __forceinline__ void cp_commit() { asm volatile("cp.async.commit_group;\n"); }
template<int N> __device__ __forceinline__ void cp_wait() {
    asm volatile("cp.async.wait_group %0;\n" :: "n"(N));
}

// ------------------------- fp16 tensor-core GEMM -----------------------------
// COMPACT: per-batch compact row layout; block exits if its 128-row window is
// past the row count (cnt0 for z==0, cnt12 for z==1,2). Padding rows compute
// garbage (never read; pad inputs are zeros anyway for QKV).
#define ASTR 40
#define BSTR 136
#define GSTAGES 4
#define STAGE_H (128 * ASTR + 32 * BSTR)
#define GEMM_SMEM_BYTES (GSTAGES * STAGE_H * 2)

template<int EPI, typename OutT, bool QKV3, bool COMPACT>
__global__ __launch_bounds__(128, 2)
void tc_gemm(const __half* __restrict__ A0, const __half* __restrict__ B0,
             const __half* __restrict__ A1, const __half* __restrict__ B1,
             const __half* __restrict__ A2, const __half* __restrict__ B2,
             const float* __restrict__ bias, OutT* __restrict__ C0,
             OutT* __restrict__ C1, OutT* __restrict__ C2,
             const int* __restrict__ cnt0, const int* __restrict__ cnt12,
             int M, int N, int K) {
    extern __shared__ __half smem[];
    const int bm = blockIdx.y * 128, bn = blockIdx.x * 128;
    if (COMPACT) {
        const int batch = bm >> 10;
        const int* cp = (!QKV3 || blockIdx.z == 0) ? cnt0 : cnt12;
        if ((bm & (S - 1)) >= cp[batch]) return;   // uniform exit
    }
    const __half* A = A0; const __half* Bm = B0; OutT* C = C0;
    if (QKV3) {
        if (blockIdx.z == 1) { A = A1; Bm = B1; C = C1; }
        else if (blockIdx.z == 2) { A = A2; Bm = B2; C = C2; }
    }
    const int tid = threadIdx.x;
    const int warp = tid >> 5, lane = tid & 31;
    const int wm = (warp & 1) * 64;
    const int wn = (warp >> 1) * 64;
    const int g = lane >> 2, t4 = lane & 3;
    const int l16 = lane & 15, lhi = (lane & 16) ? 8 : 0;

    const unsigned sbase = (unsigned)__cvta_generic_to_shared(smem);

    float c[4][8][4];
#pragma unroll
    for (int i = 0; i < 4; i++)
#pragma unroll
        for (int j = 0; j < 8; j++)
#pragma unroll
            for (int r = 0; r < 4; r++) c[i][j][r] = 0.0f;

    auto load_stage = [&](int buf, int tI) {
        __half* As = smem + buf * STAGE_H;
        __half* Bs = As + 128 * ASTR;
#pragma unroll
        for (int q = 0; q < 4; q++) {
            int ch = tid + 128 * q;
            int ar = ch >> 2, acc_ = (ch & 3) * 8;
            cp16(&As[ar * ASTR + acc_], A + (size_t)(bm + ar) * K + tI * 32 + acc_);
            int brr = ch >> 4, bcc = (ch & 15) * 8;
            cp16(&Bs[brr * BSTR + bcc], Bm + (size_t)(tI * 32 + brr) * N + bn + bcc);
        }
    };

    const int T = K / 32;
#pragma unroll
    for (int s = 0; s < GSTAGES - 1; s++) {
        load_stage(s, s);
        cp_commit();
    }

    for (int tI = 0; tI < T; tI++) {
        const int buf = tI & (GSTAGES - 1);
        cp_wait<GSTAGES - 2>();
        __syncthreads();
        if (tI + GSTAGES - 1 < T)
            load_stage((tI + GSTAGES - 1) & (GSTAGES - 1), tI + GSTAGES - 1);
        cp_commit();

        const unsigned sA = sbase + 2u * (buf * STAGE_H);
        const unsigned sB = sA + 2u * (128 * ASTR);
#pragma unroll
        for (int step = 0; step < 2; step++) {
            const int k0 = step * 16;
            unsigned af[4][4], bf[8][2];
#pragma unroll
            for (int i = 0; i < 4; i++) {
                unsigned addr = sA + 2u * ((wm + i * 16 + l16) * ASTR + k0 + lhi);
                ldsm4(af[i], addr);
            }
#pragma unroll
            for (int jp = 0; jp < 4; jp++) {
                unsigned addr = sB + 2u * ((k0 + l16) * BSTR + wn + jp * 16 + lhi);
                unsigned r[4];
                ldsm4t(r, addr);
                bf[2 * jp][0] = r[0];     bf[2 * jp][1] = r[1];
                bf[2 * jp + 1][0] = r[2]; bf[2 * jp + 1][1] = r[3];
            }
#pragma unroll
            for (int i = 0; i < 4; i++)
#pragma unroll
                for (int j = 0; j < 8; j++)
                    mma16(c[i][j], af[i], bf[j]);
        }
    }

#pragma unroll
    for (int i = 0; i < 4; i++) {
#pragma unroll
        for (int j = 0; j < 8; j++) {
            const int row0 = bm + wm + i * 16 + g;
            const int col = bn + wn + j * 8 + 2 * t4;
            float v0 = c[i][j][0], v1 = c[i][j][1], v2 = c[i][j][2], v3 = c[i][j][3];
            if (EPI >= 1) {
                float b0 = bias[col], b1 = bias[col + 1];
                v0 += b0; v1 += b1; v2 += b0; v3 += b1;
            }
            if (EPI == 2) {
                v0 *= 1.0f / (1.0f + __expf(-1.702f * v0));
                v1 *= 1.0f / (1.0f + __expf(-1.702f * v1));
                v2 *= 1.0f / (1.0f + __expf(-1.702f * v2));
                v3 *= 1.0f / (1.0f + __expf(-1.702f * v3));
            }
            if (sizeof(OutT) == 2) {
                *(__half2*)((__half*)C + (size_t)row0 * N + col) = __floats2half2_rn(v0, v1);
                *(__half2*)((__half*)C + (size_t)(row0 + 8) * N + col) = __floats2half2_rn(v2, v3);
            } else {
                float2 p0 = {v0, v1}, p1 = {v2, v3};
                *(float2*)((float*)C + (size_t)row0 * N + col) = p0;
                *(float2*)((float*)C + (size_t)(row0 + 8) * N + col) = p1;
            }
        }
    }
}

// ------------------------- compacted fp16 flash attention --------------------
#define KVSTR 72
#define KB 32

__global__ __launch_bounds__(128, 3)
void attn_tc_kernel(const __half* __restrict__ qg, const __half* __restrict__ kg,
                    const __half* __restrict__ vg,
                    const int* __restrict__ cntq_a, const int* __restrict__ cntk_a,
                    __half* __restrict__ out) {
    __shared__ __half Ks[2][KB * KVSTR];
    __shared__ __half Vs[2][KB * KVSTR];

    const int b = blockIdx.z, h = blockIdx.y;
    const int q0 = blockIdx.x * 128;
    const int cntq = cntq_a[b];
    if (q0 >= cntq) return;
    const int cntk = cntk_a[b];
    const int nkt = (cntk + KB - 1) / KB;

    const int tid = threadIdx.x;
    const int w = tid >> 5, lane = tid & 31;
    const int g = lane >> 2, t4 = lane & 3;
    const int l16 = lane & 15, lhi = (lane & 16) ? 8 : 0;
    const int l8 = lane & 7, lm = ((lane & 8) ? 8 : 0), ln16 = (lane & 16) ? 8 : 0;

    const unsigned sK0 = (unsigned)__cvta_generic_to_shared(&Ks[0][0]);
    const unsigned sK1 = (unsigned)__cvta_generic_to_shared(&Ks[1][0]);
    const unsigned sV0 = (unsigned)__cvta_generic_to_shared(&Vs[0][0]);
    const unsigned sV1 = (unsigned)__cvta_generic_to_shared(&Vs[1][0]);

    const __half2 qscale = __float2half2_rn(ATT_SCALE);
    unsigned qa[2][4][4];
#pragma unroll
    for (int i = 0; i < 2; i++) {
        const __half* Qr0 = qg + (size_t)(b * S + q0 + w * 32 + i * 16 + g) * E + h * D;
        const __half* Qr1 = Qr0 + (size_t)8 * E;
#pragma unroll
        for (int s = 0; s < 4; s++) {
            qa[i][s][0] = u2hm(*(const unsigned*)&Qr0[16 * s + 2 * t4], qscale);
            qa[i][s][1] = u2hm(*(const unsigned*)&Qr1[16 * s + 2 * t4], qscale);
            qa[i][s][2] = u2hm(*(const unsigned*)&Qr0[16 * s + 8 + 2 * t4], qscale);
            qa[i][s][3] = u2hm(*(const unsigned*)&Qr1[16 * s + 8 + 2 * t4], qscale);
        }
    }

    float oacc[2][8][4];
#pragma unroll
    for (int i = 0; i < 2; i++)
#pragma unroll
        for (int n = 0; n < 8; n++)
#pragma unroll
            for (int r = 0; r < 4; r++) oacc[i][n][r] = 0.0f;
    float lsum[2][2] = {{0.0f, 0.0f}, {0.0f, 0.0f}};

    auto load_tiles = [&](int kt, int buf) {
        int key = tid >> 2, c8 = (tid & 3) * 16;
        const __half* gk = kg + (size_t)(b * S + kt + key) * E + h * D + c8;
        const __half* gv = vg + (size_t)(b * S + kt + key) * E + h * D + c8;
        cp16(&Ks[buf][key * KVSTR + c8], gk);
        cp16(&Ks[buf][key * KVSTR + c8 + 8], gk + 8);
        cp16(&Vs[buf][key * KVSTR + c8], gv);
        cp16(&Vs[buf][key * KVSTR + c8 + 8], gv + 8);
    };

    load_tiles(0, 0);
    cp_commit();

    for (int kb = 0; kb < nkt; kb++) {
        const int buf = kb & 1;
        if (kb + 1 < nkt) {
            load_tiles((kb + 1) * KB, buf ^ 1);
            cp_commit();
            cp_wait<1>();
        } else {
            cp_wait<0>();
        }
        __syncthreads();

        const unsigned sK = buf ? sK1 : sK0;
        const unsigned sV = buf ? sV1 : sV0;

        float sc[2][4][4];
#pragma unroll
        for (int i = 0; i < 2; i++)
#pragma unroll
            for (int j = 0; j < 4; j++)
#pragma unroll
                for (int r = 0; r < 4; r++) sc[i][j][r] = 0.0f;
#pragma unroll
        for (int s = 0; s < 4; s++) {
#pragma unroll
            for (int jp = 0; jp < 2; jp++) {
                unsigned addr = sK + 2u * ((jp * 16 + l8 + ln16) * KVSTR + 16 * s + lm);
                unsigned r[4];
                ldsm4(r, addr);
                unsigned bf0[2] = {r[0], r[1]};
                unsigned bf1[2] = {r[2], r[3]};
#pragma unroll
                for (int i = 0; i < 2; i++) {
                    mma16(sc[i][2 * jp], qa[i][s], bf0);
                    mma16(sc[i][2 * jp + 1], qa[i][s], bf1);
                }
            }
        }

        const int kbase = kb * KB;
        unsigned pp[2][4][2];
#pragma unroll
        for (int i = 0; i < 2; i++) {
#pragma unroll
            for (int j = 0; j < 4; j++) {
                const int c0 = 8 * j + 2 * t4;
                float m0 = (kbase + c0 < cntk) ? 1.0f : 0.0f;
                float m1 = (kbase + c0 + 1 < cntk) ? 1.0f : 0.0f;
                float p0 = __expf(sc[i][j][0]) * m0;
                float p1 = __expf(sc[i][j][1]) * m1;
                float p2 = __expf(sc[i][j][2]) * m0;
                float p3 = __expf(sc[i][j][3]) * m1;
                lsum[i][0] += p0 + p1;
                lsum[i][1] += p2 + p3;
                pp[i][j][0] = h2u(__floats2half2_rn(p0, p1));
                pp[i][j][1] = h2u(__floats2half2_rn(p2, p3));
            }
        }

#pragma unroll
        for (int s = 0; s < 2; s++) {
            unsigned pa[2][4];
#pragma unroll
            for (int i = 0; i < 2; i++) {
                pa[i][0] = pp[i][2 * s][0]; pa[i][1] = pp[i][2 * s][1];
                pa[i][2] = pp[i][2 * s + 1][0]; pa[i][3] = pp[i][2 * s + 1][1];
            }
#pragma unroll
            for (int np = 0; np < 4; np++) {
                unsigned addr = sV + 2u * ((16 * s + l16) * KVSTR + np * 16 + lhi);
                unsigned r[4];
                ldsm4t(r, addr);
                unsigned bf0[2] = {r[0], r[1]};
                unsigned bf1[2] = {r[2], r[3]};
#pragma unroll
                for (int i = 0; i < 2; i++) {
                    mma16(oacc[i][2 * np], pa[i], bf0);
                    mma16(oacc[i][2 * np + 1], pa[i], bf1);
                }
            }
        }
        __syncthreads();
    }

#pragma unroll
    for (int i = 0; i < 2; i++) {
        float l0 = lsum[i][0], l1 = lsum[i][1];
        l0 += __shfl_xor_sync(0xffffffffu, l0, 1);
        l0 += __shfl_xor_sync(0xffffffffu, l0, 2);
        l1 += __shfl_xor_sync(0xffffffffu, l1, 1);
        l1 += __shfl_xor_sync(0xffffffffu, l1, 2);

        const int slot0 = b * S + q0 + w * 32 + i * 16 + g;
        const float inv0 = 1.0f / l0;
        const float inv1 = 1.0f / l1;
        __half* o0 = out + (size_t)slot0 * E + h * D;
        __half* o1 = o0 + (size_t)8 * E;
#pragma unroll
        for (int n = 0; n < 8; n++) {
            const int c0 = 8 * n + 2 * t4;
            *(__half2*)(o0 + c0) = __floats2half2_rn(oacc[i][n][0] * inv0, oacc[i][n][1] * inv0);
            *(__half2*)(o1 + c0) = __floats2half2_rn(oacc[i][n][2] * inv1, oacc[i][n][3] * inv1);
        }
    }
}

// ------------------------- layernorm variants --------------------------------
template<int MODE, typename OutT>
__global__ __launch_bounds__(256)
void ln_kernel(const float* __restrict__ x, const float* __restrict__ res,
               const float* __restrict__ g, const float* __restrict__ bb,
               const int* __restrict__ idx_or_mask, const int* __restrict__ qslot,
               OutT* __restrict__ out) {
    __shared__ float s1[256], s2[256];
    const int blk = blockIdx.x;
    const int tid = threadIdx.x;

    int xrow, resrow, orow;
    bool active;
    if (MODE == 0) {
        int orig = idx_or_mask[blk];     // qidx
        active = (orig >= 0);
        xrow = blk; resrow = (blk & ~(S - 1)) + (active ? orig : 0); orow = blk;
    } else {
        active = (idx_or_mask[blk] != 0);   // mq
        int r = active ? qslot[blk] : 0;
        xrow = (blk & ~(S - 1)) + r; resrow = blk; orow = blk;
    }

    if (!active) {
        for (int i = 0; i < 4; i++) {
            int c = tid + i * 256;
            if (sizeof(OutT) == 2) ((__half*)out)[(size_t)orow * E + c] = __float2half(0.0f);
            else                   ((float*)out)[(size_t)orow * E + c] = 0.0f;
        }
        return;
    }

    const float* xr = x + (size_t)xrow * E;
    const float* rr = res + (size_t)resrow * E;
    float v[4];
    float s = 0.0f, sq = 0.0f;
#pragma unroll
    for (int i = 0; i < 4; i++) {
        int c = tid + i * 256;
        float t = xr[c];
        if (MODE == 1) t += rr[c];
        v[i] = t; s += t; sq += t * t;
    }
    s1[tid] = s; s2[tid] = sq;
    __syncthreads();
    for (int off = 128; off > 0; off >>= 1) {
        if (tid < off) { s1[tid] += s1[tid + off]; s2[tid] += s2[tid + off]; }
        __syncthreads();
    }
    float mu = s1[0] * (1.0f / E);
    float var = s2[0] * (1.0f / E) - mu * mu;
    float rstd = rsqrtf(var + 1e-5f);
#pragma unroll
    for (int i = 0; i < 4; i++) {
        int c = tid + i * 256;
        float y = (v[i] - mu) * rstd * g[c] + bb[c];
        float o = (MODE == 0) ? (y + rr[c]) : y;
        if (sizeof(OutT) == 2) ((__half*)out)[(size_t)orow * E + c] = __float2half(o);
        else                   ((float*)out)[(size_t)orow * E + c] = o;
    }
}

// ------------------------- launch -------------------------------------------
extern "C" void kernel_launch(void* const* d_in, const int* in_sizes, int n_in,
                              void* d_out, int out_size) {
    const float* value = (const float*)d_in[0];
    const float* key   = (const float*)d_in[1];
    const float* query = (const float*)d_in[2];
    const void*  mask_k_raw = d_in[3];
    const void*  mask_q_raw = d_in[4];
    const float* Wv = (const float*)d_in[5];
    const float* Wk = (const float*)d_in[6];
    const float* Wq = (const float*)d_in[7];
    const float* Wo = (const float*)d_in[8];
    const float* ln0_g = (const float*)d_in[9];
    const float* ln0_b = (const float*)d_in[10];
    const float* W1 = (const float*)d_in[11];
    const float* b1 = (const float*)d_in[12];
    const float* W2 = (const float*)d_in[13];
    const float* b2 = (const float*)d_in[14];
    const float* ln1_g = (const float*)d_in[15];
    const float* ln1_b = (const float*)d_in[16];
    float* out = (float*)d_out;

    __half *qin, *kin, *vin, *Wqh, *Wkh, *Wvh, *Woh, *W1h, *W2h;
    __half *qg, *kg, *vg, *attnh, *hh, *g1h;
    float *att, *ff;
    int *mq, *mk, *qidx, *kidx, *qslot, *cntq, *cntk;
    cudaGetSymbolAddress((void**)&qin,  g_qin);
    cudaGetSymbolAddress((void**)&kin,  g_kin);
    cudaGetSymbolAddress((void**)&vin,  g_vin);
    cudaGetSymbolAddress((void**)&Wqh,  g_Wqh);
    cudaGetSymbolAddress((void**)&Wkh,  g_Wkh);
    cudaGetSymbolAddress((void**)&Wvh,  g_Wvh);
    cudaGetSymbolAddress((void**)&Woh,  g_Woh);
    cudaGetSymbolAddress((void**)&W1h,  g_W1h);
    cudaGetSymbolAddress((void**)&W2h,  g_W2h);
    cudaGetSymbolAddress((void**)&qg,   g_qg);
    cudaGetSymbolAddress((void**)&kg,   g_kg);
    cudaGetSymbolAddress((void**)&vg,   g_vg);
    cudaGetSymbolAddress((void**)&attnh,g_attnh);
    cudaGetSymbolAddress((void**)&hh,   g_hh);
    cudaGetSymbolAddress((void**)&g1h,  g_g1h);
    cudaGetSymbolAddress((void**)&att,  g_att);
    cudaGetSymbolAddress((void**)&ff,   g_ff);
    cudaGetSymbolAddress((void**)&mq,   g_mq);
    cudaGetSymbolAddress((void**)&mk,   g_mk);
    cudaGetSymbolAddress((void**)&qidx, g_qidx);
    cudaGetSymbolAddress((void**)&kidx, g_kidx);
    cudaGetSymbolAddress((void**)&qslot,g_qslot);
    cudaGetSymbolAddress((void**)&cntq, g_cntq);
    cudaGetSymbolAddress((void**)&cntk, g_cntk);

    cudaFuncSetAttribute(tc_gemm<0, __half, true, true>,  cudaFuncAttributeMaxDynamicSharedMemorySize, GEMM_SMEM_BYTES);
    cudaFuncSetAttribute(tc_gemm<0, float, false, true>,  cudaFuncAttributeMaxDynamicSharedMemorySize, GEMM_SMEM_BYTES);
    cudaFuncSetAttribute(tc_gemm<1, float, false, true>,  cudaFuncAttributeMaxDynamicSharedMemorySize, GEMM_SMEM_BYTES);
    cudaFuncSetAttribute(tc_gemm<2, __half, false, true>, cudaFuncAttributeMaxDynamicSharedMemorySize, GEMM_SMEM_BYTES);

    mask_convert2_kernel<<<1, 256>>>(mask_k_raw, mk, mask_q_raw, mq, NROWS);
    build_index_kernel<<<B, 1024>>>(mq, mk, qidx, kidx, qslot, cntq, cntk);

    // weights fp32->fp16
    f2h_w_kernel<<<dim3(128, 6), 256>>>(Wq, Wqh, Wk, Wkh, Wv, Wvh, Wo, Woh,
                                        W1, W1h, W2, W2h);

    // activations: fused gather (compact) + fp32->fp16
    gav_kernel<<<dim3(NROWS / 8, 3), 256>>>(query, key, value, qidx, kidx,
                                            qin, kin, vin);

    dim3 gE3(E / 128, NROWS / 128, 3);
    dim3 gE(E / 128, NROWS / 128);
    dim3 gF(FFDIM / 128, NROWS / 128);

    // QKV projections on compact rows (z=0 -> cntq, z=1,2 -> cntk)
    tc_gemm<0, __half, true, true><<<gE3, 128, GEMM_SMEM_BYTES>>>(
        qin, Wqh, kin, Wkh, vin, Wvh, nullptr, qg, kg, vg, cntq, cntk, NROWS, E, E);

    attn_tc_kernel<<<dim3(S / 128, H, B), 128>>>(qg, kg, vg, cntq, cntk, attnh);

    tc_gemm<0, float, false, true><<<gE, 128, GEMM_SMEM_BYTES>>>(
        attnh, Woh, nullptr, nullptr, nullptr, nullptr, nullptr,
        att, nullptr, nullptr, cntq, nullptr, NROWS, E, E);

    ln_kernel<0, __half><<<NROWS, 256>>>(att, query, ln0_g, ln0_b, qidx, qslot, hh);

    tc_gemm<2, __half, false, true><<<gF, 128, GEMM_SMEM_BYTES>>>(
        hh, W1h, nullptr, nullptr, nullptr, nullptr, b1,
        g1h, nullptr, nullptr, cntq, nullptr, NROWS, FFDIM, E);
    tc_gemm<1, float, false, true><<<gE, 128, GEMM_SMEM_BYTES>>>(
        g1h, W2h, nullptr, nullptr, nullptr, nullptr, b2,
        ff, nullptr, nullptr, cntq, nullptr, NROWS, E, FFDIM);

    ln_kernel<1, float><<<NROWS, 256>>>(ff, query, ln1_g, ln1_b, mq, qslot, out);
}